// round 13
// baseline (speedup 1.0000x reference)
#include <cuda_runtime.h>
#include <cuda_bf16.h>

#define D_MODEL 1024
#define NHEADS  16
#define DK      64
#define BATCH   2
#define SEQ     2048
#define MROWS   (BATCH*SEQ)   // 4096
#define WPR     512           // packed bf16x2 words per 1024-float row

// ---------------------------------------------------------------------------
// Scratch (device globals; allocation-free per harness rules).
// ---------------------------------------------------------------------------
__device__ unsigned g_Xh[(size_t)MROWS*WPR];
__device__ unsigned g_Xl[(size_t)MROWS*WPR];
__device__ unsigned g_Wh[(size_t)4*D_MODEL*WPR];   // slots: Wq,Wk,Wv,Wo
__device__ unsigned g_Wl[(size_t)4*D_MODEL*WPR];
__device__ unsigned g_Qh[(size_t)BATCH*NHEADS*SEQ*32];
__device__ unsigned g_Ql[(size_t)BATCH*NHEADS*SEQ*32];
__device__ unsigned g_Kh[(size_t)BATCH*NHEADS*SEQ*32];
__device__ unsigned g_Kl[(size_t)BATCH*NHEADS*SEQ*32];
__device__ float    g_V [(size_t)MROWS*D_MODEL];
__device__ unsigned g_Vth[(size_t)BATCH*NHEADS*DK*(SEQ/2)];
__device__ unsigned g_Vtl[(size_t)BATCH*NHEADS*DK*(SEQ/2)];
__device__ unsigned g_Oh[(size_t)MROWS*WPR];
__device__ unsigned g_Ol[(size_t)MROWS*WPR];

// ---------------------------------------------------------------------------
__device__ __forceinline__ float ex2f(float x) {
    float r; asm("ex2.approx.f32 %0, %1;" : "=f"(r) : "f"(x)); return r;
}
__device__ __forceinline__ unsigned pack2(float x, float y) {
    __nv_bfloat162 h = __floats2bfloat162_rn(x, y);
    return reinterpret_cast<unsigned&>(h);
}
__device__ __forceinline__ void split2(float x, float y, unsigned& hi, unsigned& lo) {
    __nv_bfloat162 h = __floats2bfloat162_rn(x, y);
    float xr = x - __bfloat162float(h.x);
    float yr = y - __bfloat162float(h.y);
    hi = reinterpret_cast<unsigned&>(h);
    lo = pack2(xr, yr);
}
__device__ __forceinline__ void mma_bf16(float* c, const unsigned* a, const unsigned* b) {
    asm volatile(
        "mma.sync.aligned.m16n8k16.row.col.f32.bf16.bf16.f32 "
        "{%0,%1,%2,%3}, {%4,%5,%6,%7}, {%8,%9}, {%0,%1,%2,%3};\n"
        : "+f"(c[0]), "+f"(c[1]), "+f"(c[2]), "+f"(c[3])
        : "r"(a[0]), "r"(a[1]), "r"(a[2]), "r"(a[3]), "r"(b[0]), "r"(b[1]));
}
__device__ __forceinline__ void ldsm4(unsigned* r, unsigned addr) {
    asm volatile("ldmatrix.sync.aligned.m8n8.x4.shared.b16 {%0,%1,%2,%3}, [%4];"
                 : "=r"(r[0]), "=r"(r[1]), "=r"(r[2]), "=r"(r[3]) : "r"(addr));
}
__device__ __forceinline__ unsigned ldsm_a_off(int lane, int stride_words) {
    int row = lane & 15;
    int wrd = (lane >> 4) * 4;
    return (unsigned)((row * stride_words + wrd) * 4);
}
__device__ __forceinline__ unsigned ldsm_b_off(int lane, int stride_words) {
    int jm  = lane & 7;
    int sel = lane >> 3;                 // 0..3
    int row = ((sel >> 1) << 3) + jm;    // 0..7 or 8..15
    int wrd = (sel & 1) * 4;
    return (unsigned)((row * stride_words + wrd) * 4);
}
__device__ __forceinline__ void cpa16(unsigned dst, const unsigned* src) {
    asm volatile("cp.async.cg.shared.global [%0], [%1], 16;\n" :: "r"(dst), "l"(src) : "memory");
}
__device__ __forceinline__ void cpa_commit() { asm volatile("cp.async.commit_group;\n" ::: "memory"); }
__device__ __forceinline__ void cpa_wait0()  { asm volatile("cp.async.wait_group 0;\n" ::: "memory"); }
__device__ __forceinline__ void cpa_wait1()  { asm volatile("cp.async.wait_group 1;\n" ::: "memory"); }

// ---------------------------------------------------------------------------
// Pre-split: f32 rows -> packed bf16x2 hi/lo words
// ---------------------------------------------------------------------------
__global__ void split_pack(const float* __restrict__ src, unsigned* __restrict__ dh,
                           unsigned* __restrict__ dl, int nwords)
{
    int i = blockIdx.x * 256 + threadIdx.x;
    if (i < nwords) {
        float2 v = ((const float2*)src)[i];
        unsigned hi, lo; split2(v.x, v.y, hi, lo);
        dh[i] = hi; dl[i] = lo;
    }
}

// ---------------------------------------------------------------------------
// bf16x3 GEMM on pre-split packed operands, attention-style feeding:
// 3-stage cp.async ring -> ldmatrix -> MMA. C[128x128], BK=16, 2 CTAs/SM.
// 256 threads = 8 warps (2My x 4Nx), warp tile 64x32.
// ---------------------------------------------------------------------------
#define AW 12
#define SEG (128*AW)                          // words per array (1536)
#define STGW (4*SEG)                          // words per stage (Ah,Al,Bh,Bl)
#define NST 3
#define GEMM_SMEM_BYTES (NST*STGW*4)          // 73728 B

__device__ __forceinline__ void gemm_packed(
    const unsigned* __restrict__ Ah_g, const unsigned* __restrict__ Al_g,
    const unsigned* __restrict__ Bh_g, const unsigned* __restrict__ Bl_g,
    float (&c)[4][4][4], unsigned* sm)
{
    const unsigned smb = (unsigned)__cvta_generic_to_shared(sm);
    const int tid  = threadIdx.x;
    const int warp = tid >> 5, lane = tid & 31;
    const int wy = warp >> 2;          // 0..1 (M)
    const int wx = warp & 3;           // 0..3 (N)
    const int pr = tid >> 1;           // loader row 0..127
    const int pc = (tid & 1) * 4;      // word chunk 0 or 4

    const unsigned aoff = ldsm_a_off(lane, AW);
    const unsigned boff = ldsm_b_off(lane, AW);
    const unsigned soff = (unsigned)((pr * AW + pc) * 4);

#pragma unroll
    for (int mi = 0; mi < 4; mi++)
#pragma unroll
        for (int ni = 0; ni < 4; ni++)
#pragma unroll
            for (int r = 0; r < 4; r++) c[mi][ni][r] = 0.f;

    auto load_stage = [&](int st, int kt) {
        const unsigned base = smb + (unsigned)(st * STGW * 4);
        const size_t gs = (size_t)pr * WPR + (size_t)kt * 8 + pc;
        cpa16(base + soff,             Ah_g + gs);
        cpa16(base + SEG*4 + soff,     Al_g + gs);
        cpa16(base + 2*SEG*4 + soff,   Bh_g + gs);
        cpa16(base + 3*SEG*4 + soff,   Bl_g + gs);
        cpa_commit();
    };

    load_stage(0, 0);
    load_stage(1, 1);

    int st = 0;
    for (int kt = 0; kt < 64; kt++) {
        if (kt + 1 < 64) cpa_wait1(); else cpa_wait0();
        __syncthreads();
        if (kt + 2 < 64) {
            int ns = st + 2; if (ns >= NST) ns -= NST;
            load_stage(ns, kt + 2);
        } else {
            cpa_commit();                  // keep wait_group 1 semantics
        }

        const unsigned AhB = smb + (unsigned)(st * STGW * 4);
        const unsigned AlB = AhB + SEG*4;
        const unsigned BhB = AhB + 2*SEG*4;
        const unsigned BlB = AhB + 3*SEG*4;

        unsigned bh[4][2], bl[4][2];
#pragma unroll
        for (int p = 0; p < 2; p++) {
            const unsigned nbase = (unsigned)((wx * 32 + p * 16) * AW * 4);
            unsigned r4[4];
            ldsm4(r4, BhB + nbase + boff);
            bh[2*p][0] = r4[0]; bh[2*p][1] = r4[1];
            bh[2*p+1][0] = r4[2]; bh[2*p+1][1] = r4[3];
            ldsm4(r4, BlB + nbase + boff);
            bl[2*p][0] = r4[0]; bl[2*p][1] = r4[1];
            bl[2*p+1][0] = r4[2]; bl[2*p+1][1] = r4[3];
        }
#pragma unroll
        for (int mi = 0; mi < 4; mi++) {
            const unsigned rbase = (unsigned)((wy * 64 + mi * 16) * AW * 4);
            unsigned ah[4], al[4];
            ldsm4(ah, AhB + rbase + aoff);
            ldsm4(al, AlB + rbase + aoff);
#pragma unroll
            for (int ni = 0; ni < 4; ni++) mma_bf16(c[mi][ni], ah, bh[ni]);
#pragma unroll
            for (int ni = 0; ni < 4; ni++) mma_bf16(c[mi][ni], ah, bl[ni]);
#pragma unroll
            for (int ni = 0; ni < 4; ni++) mma_bf16(c[mi][ni], al, bh[ni]);
        }
        st = (st == NST - 1) ? 0 : st + 1;
    }
}

// z=0 -> Q packed (prescaled), z=1 -> K packed, z=2 -> V f32
__global__ __launch_bounds__(256, 2)
void qkv_gemm()
{
    extern __shared__ unsigned gsm[];
    const int z = blockIdx.z;
    const unsigned* Ah_g = g_Xh + (size_t)blockIdx.y * 128 * WPR;
    const unsigned* Al_g = g_Xl + (size_t)blockIdx.y * 128 * WPR;
    const size_t wslot = (size_t)z * D_MODEL * WPR + (size_t)blockIdx.x * 128 * WPR;
    const unsigned* Bh_g = g_Wh + wslot;
    const unsigned* Bl_g = g_Wl + wslot;

    float c[4][4][4];
    gemm_packed(Ah_g, Al_g, Bh_g, Bl_g, c, gsm);

    const int tid  = threadIdx.x;
    const int warp = tid >> 5, lane = tid & 31;
    const int g = lane >> 2, t = lane & 3;
    const int wy = warp >> 2, wx = warp & 3;

    if (z < 2) {
        unsigned* Ph = z ? g_Kh : g_Qh;
        unsigned* Pl = z ? g_Kl : g_Ql;
        const float scale = z ? 1.f : 0.125f * 1.4426950408889634f;
#pragma unroll
        for (int mi = 0; mi < 4; mi++) {
            int row = blockIdx.y * 128 + wy * 64 + mi * 16 + g;
            int bb = row >> 11, s = row & 2047;
#pragma unroll
            for (int ni = 0; ni < 4; ni++) {
                int col = blockIdx.x * 128 + wx * 32 + ni * 8 + 2 * t;
                int hh = col >> 6, dkw = (col & 63) >> 1;
                size_t w = (((size_t)bb * NHEADS + hh) * SEQ + s) * 32 + dkw;
                unsigned hi, lo;
                split2(c[mi][ni][0] * scale, c[mi][ni][1] * scale, hi, lo);
                Ph[w] = hi; Pl[w] = lo;
                split2(c[mi][ni][2] * scale, c[mi][ni][3] * scale, hi, lo);
                Ph[w + 8*32] = hi; Pl[w + 8*32] = lo;
            }
        }
    } else {
#pragma unroll
        for (int mi = 0; mi < 4; mi++) {
            int row = blockIdx.y * 128 + wy * 64 + mi * 16 + g;
#pragma unroll
            for (int ni = 0; ni < 4; ni++) {
                int col = blockIdx.x * 128 + wx * 32 + ni * 8 + 2 * t;
                *(float2*)&g_V[(size_t)row * 1024 + col] =
                    make_float2(c[mi][ni][0], c[mi][ni][1]);
                *(float2*)&g_V[(size_t)(row + 8) * 1024 + col] =
                    make_float2(c[mi][ni][2], c[mi][ni][3]);
            }
        }
    }
}

__global__ __launch_bounds__(256, 2)
void proj_gemm(float* __restrict__ Out)
{
    extern __shared__ unsigned gsm[];
    const unsigned* Ah_g = g_Oh + (size_t)blockIdx.y * 128 * WPR;
    const unsigned* Al_g = g_Ol + (size_t)blockIdx.y * 128 * WPR;
    const size_t wslot = (size_t)3 * D_MODEL * WPR + (size_t)blockIdx.x * 128 * WPR;
    const unsigned* Bh_g = g_Wh + wslot;
    const unsigned* Bl_g = g_Wl + wslot;

    float c[4][4][4];
    gemm_packed(Ah_g, Al_g, Bh_g, Bl_g, c, gsm);

    const int tid  = threadIdx.x;
    const int warp = tid >> 5, lane = tid & 31;
    const int g = lane >> 2, t = lane & 3;
    const int wy = warp >> 2, wx = warp & 3;
#pragma unroll
    for (int mi = 0; mi < 4; mi++) {
        int row = blockIdx.y * 128 + wy * 64 + mi * 16 + g;
#pragma unroll
        for (int ni = 0; ni < 4; ni++) {
            int col = blockIdx.x * 128 + wx * 32 + ni * 8 + 2 * t;
            *(float2*)&Out[(size_t)row * 1024 + col] =
                make_float2(c[mi][ni][0], c[mi][ni][1]);
            *(float2*)&Out[(size_t)(row + 8) * 1024 + col] =
                make_float2(c[mi][ni][2], c[mi][ni][3]);
        }
    }
}

// V transpose + split: g_V [b,s,h*64+dk] -> g_Vt{h,l} [b,h][dk][s/2 words]
__global__ __launch_bounds__(256)
void vtrans()
{
    __shared__ float smv[128 * 65];
    const int sc = blockIdx.x, h = blockIdx.y, b = blockIdx.z;
    const int tid = threadIdx.x;
    const float* src = g_V + ((size_t)b * SEQ + sc * 128) * D_MODEL + h * DK;
#pragma unroll
    for (int l = 0; l < 8; l++) {
        int idx = tid + l * 256;
        int r = idx >> 4, cc = (idx & 15) * 4;
        float4 v = *(const float4*)(src + (size_t)r * D_MODEL + cc);
        smv[r*65 + cc] = v.x; smv[r*65 + cc + 1] = v.y;
        smv[r*65 + cc + 2] = v.z; smv[r*65 + cc + 3] = v.w;
    }
    __syncthreads();
    const size_t dbase = ((size_t)(b * NHEADS + h) * DK) * 1024 + sc * 64;
#pragma unroll
    for (int l = 0; l < 16; l++) {
        int idx = tid + l * 256;
        int dk = idx >> 6, sw = idx & 63;
        unsigned hi, lo;
        split2(smv[(2*sw) * 65 + dk], smv[(2*sw + 1) * 65 + dk], hi, lo);
        g_Vth[dbase + (size_t)dk * 1024 + sw] = hi;
        g_Vtl[dbase + (size_t)dk * 1024 + sw] = lo;
    }
}

// ---------------------------------------------------------------------------
// Flash attention, bf16x3, cp.async double-buffered K/V, P in registers,
// ldmatrix fragment loads. Emits O pre-split/packed for proj_gemm.
// ---------------------------------------------------------------------------
#define KWS 36
#define VWS 68
#define ATTN_SMEM_BYTES ((2*128*KWS*2 + 2*64*VWS*2) * 4)   // 143360

__global__ __launch_bounds__(256, 1)
void attn_fwd()
{
    extern __shared__ unsigned sm[];
    const unsigned smb  = (unsigned)__cvta_generic_to_shared(sm);
    const unsigned KshB = smb;
    const unsigned KslB = smb + 2*128*KWS*4;
    const unsigned VshB = KslB + 2*128*KWS*4;
    const unsigned VslB = VshB + 2*64*VWS*4;

    const int qb = (gridDim.x - 1) - blockIdx.x;
    const int bh = blockIdx.z * NHEADS + blockIdx.y;
    const int tid = threadIdx.x, warp = tid >> 5, lane = tid & 31;
    const int g = lane >> 2, t = lane & 3;
    const int kr0 = tid >> 3, kch = (tid & 7) * 4;
    const int vd0 = tid >> 4, vch = (tid & 15) * 4;

    const unsigned boffK = ldsm_b_off(lane, KWS);
    const unsigned boffV = ldsm_b_off(lane, VWS);

    auto load_kv = [&](int buf, int j) {
        const size_t kbase = ((size_t)bh * SEQ + (size_t)j * 128) * 32;
#pragma unroll
        for (int l = 0; l < 4; l++) {
            int r = kr0 + l * 32;
            unsigned doff = (unsigned)((r * KWS + kch) * 4);
            cpa16(KshB + buf*(128*KWS*4) + doff, g_Kh + kbase + r*32 + kch);
            cpa16(KslB + buf*(128*KWS*4) + doff, g_Kl + kbase + r*32 + kch);
        }
        const size_t vbase = (size_t)bh * DK * 1024 + (size_t)j * 64;
#pragma unroll
        for (int l = 0; l < 4; l++) {
            int dk = vd0 + l * 16;
            unsigned doff = (unsigned)((dk * VWS + vch) * 4);
            cpa16(VshB + buf*(64*VWS*4) + doff, g_Vth + vbase + (size_t)dk*1024 + vch);
            cpa16(VslB + buf*(64*VWS*4) + doff, g_Vtl + vbase + (size_t)dk*1024 + vch);
        }
        cpa_commit();
    };

    load_kv(0, 0);

    unsigned qh[4][4], ql[4][4];
    {
        const size_t qbase = ((size_t)bh * SEQ + (size_t)qb * 128 + warp * 16 + g) * 32;
#pragma unroll
        for (int kt = 0; kt < 4; kt++) {
            qh[kt][0] = g_Qh[qbase + kt*8 + t];
            qh[kt][1] = g_Qh[qbase + 8*32 + kt*8 + t];
            qh[kt][2] = g_Qh[qbase + kt*8 + 4 + t];
            qh[kt][3] = g_Qh[qbase + 8*32 + kt*8 + 4 + t];
            ql[kt][0] = g_Ql[qbase + kt*8 + t];
            ql[kt][1] = g_Ql[qbase + 8*32 + kt*8 + t];
            ql[kt][2] = g_Ql[qbase + kt*8 + 4 + t];
            ql[kt][3] = g_Ql[qbase + 8*32 + kt*8 + 4 + t];
        }
    }

    float m0 = -1e30f, m1 = -1e30f, l0 = 0.f, l1 = 0.f;
    float o[8][4];
#pragma unroll
    for (int ni = 0; ni < 8; ni++)
#pragma unroll
        for (int r = 0; r < 4; r++) o[ni][r] = 0.f;

    const int prow0 = warp * 16 + g;
    const int prow1 = prow0 + 8;

    cpa_wait0();
    __syncthreads();

    int buf = 0;
    for (int j = 0; j <= qb; j++) {
        if (j < qb) load_kv(buf ^ 1, j + 1);

        const unsigned KhB_t = KshB + (unsigned)(buf * 128*KWS*4);
        const unsigned KlB_t = KslB + (unsigned)(buf * 128*KWS*4);
        const unsigned VhB_t = VshB + (unsigned)(buf * 64*VWS*4);
        const unsigned VlB_t = VslB + (unsigned)(buf * 64*VWS*4);

        float s[16][4];
#pragma unroll
        for (int ni = 0; ni < 16; ni++) {
            s[ni][0] = 0.f; s[ni][1] = 0.f; s[ni][2] = 0.f; s[ni][3] = 0.f;
        }
#pragma unroll
        for (int kt = 0; kt < 4; kt++) {
#pragma unroll
            for (int p = 0; p < 8; p++) {
                unsigned nb = (unsigned)(p * 16 * KWS * 4) + (unsigned)(kt * 32);
                unsigned kh[4], kl[4];
                ldsm4(kh, KhB_t + nb + boffK);
                ldsm4(kl, KlB_t + nb + boffK);
                mma_bf16(s[2*p],   qh[kt], kh);
                mma_bf16(s[2*p],   qh[kt], kl);
                mma_bf16(s[2*p],   ql[kt], kh);
                mma_bf16(s[2*p+1], qh[kt], kh + 2);
                mma_bf16(s[2*p+1], qh[kt], kl + 2);
                mma_bf16(s[2*p+1], ql[kt], kh + 2);
            }
        }

        if (j == qb) {
#pragma unroll
            for (int ni = 0; ni < 16; ni++) {
                int cb = ni * 8 + 2 * t;
                if (cb     > prow0) s[ni][0] = -1e30f;
                if (cb + 1 > prow0) s[ni][1] = -1e30f;
                if (cb     > prow1) s[ni][2] = -1e30f;
                if (cb + 1 > prow1) s[ni][3] = -1e30f;
            }
        }

        float rm0 = -1e30f, rm1 = -1e30f;
#pragma unroll
        for (int ni = 0; ni < 16; ni++) {
            rm0 = fmaxf(rm0, fmaxf(s[ni][0], s[ni][1]));
            rm1 = fmaxf(rm1, fmaxf(s[ni][2], s[ni][3]));
        }
        rm0 = fmaxf(rm0, __shfl_xor_sync(0xffffffffu, rm0, 1));
        rm0 = fmaxf(rm0, __shfl_xor_sync(0xffffffffu, rm0, 2));
        rm1 = fmaxf(rm1, __shfl_xor_sync(0xffffffffu, rm1, 1));
        rm1 = fmaxf(rm1, __shfl_xor_sync(0xffffffffu, rm1, 2));

        float mn0 = fmaxf(m0, rm0), mn1 = fmaxf(m1, rm1);
        float a0 = ex2f(m0 - mn0), a1 = ex2f(m1 - mn1);
        float rs0 = 0.f, rs1 = 0.f;
#pragma unroll
        for (int ni = 0; ni < 16; ni++) {
            s[ni][0] = ex2f(s[ni][0] - mn0);
            s[ni][1] = ex2f(s[ni][1] - mn0);
            s[ni][2] = ex2f(s[ni][2] - mn1);
            s[ni][3] = ex2f(s[ni][3] - mn1);
            rs0 += s[ni][0] + s[ni][1];
            rs1 += s[ni][2] + s[ni][3];
        }
        rs0 += __shfl_xor_sync(0xffffffffu, rs0, 1);
        rs0 += __shfl_xor_sync(0xffffffffu, rs0, 2);
        rs1 += __shfl_xor_sync(0xffffffffu, rs1, 1);
        rs1 += __shfl_xor_sync(0xffffffffu, rs1, 2);
        l0 = l0 * a0 + rs0;  m0 = mn0;
        l1 = l1 * a1 + rs1;  m1 = mn1;
#pragma unroll
        for (int ni = 0; ni < 8; ni++) {
            o[ni][0] *= a0; o[ni][1] *= a0;
            o[ni][2] *= a1; o[ni][3] *= a1;
        }

#pragma unroll
        for (int kt = 0; kt < 8; kt++) {
            unsigned ph[4], pl[4];
            split2(s[2*kt][0],   s[2*kt][1],   ph[0], pl[0]);
            split2(s[2*kt][2],   s[2*kt][3],   ph[1], pl[1]);
            split2(s[2*kt+1][0], s[2*kt+1][1], ph[2], pl[2]);
            split2(s[2*kt+1][2], s[2*kt+1][3], ph[3], pl[3]);
#pragma unroll
            for (int p = 0; p < 4; p++) {
                unsigned nb = (unsigned)(p * 16 * VWS * 4) + (unsigned)(kt * 32);
                unsigned vh[4], vl[4];
                ldsm4(vh, VhB_t + nb + boffV);
                ldsm4(vl, VlB_t + nb + boffV);
                mma_bf16(o[2*p],   ph, vh);
                mma_bf16(o[2*p],   ph, vl);
                mma_bf16(o[2*p],   pl, vh);
                mma_bf16(o[2*p+1], ph, vh + 2);
                mma_bf16(o[2*p+1], ph, vl + 2);
                mma_bf16(o[2*p+1], pl, vh + 2);
            }
        }

        if (j < qb) cpa_wait0();
        __syncthreads();
        buf ^= 1;
    }

    // normalize + write O packed bf16 hi/lo (word layout matches g_Xh/g_Xl)
    float inv0 = 1.f / l0, inv1 = 1.f / l1;
    const size_t orow = (size_t)blockIdx.z * SEQ + (size_t)qb * 128;
    const int hwbase = blockIdx.y * 32;
#pragma unroll
    for (int ni = 0; ni < 8; ni++) {
        int w = hwbase + ni * 4 + t;
        unsigned hi, lo;
        split2(o[ni][0] * inv0, o[ni][1] * inv0, hi, lo);
        g_Oh[(orow + prow0) * WPR + w] = hi;
        g_Ol[(orow + prow0) * WPR + w] = lo;
        split2(o[ni][2] * inv1, o[ni][3] * inv1, hi, lo);
        g_Oh[(orow + prow1) * WPR + w] = hi;
        g_Ol[(orow + prow1) * WPR + w] = lo;
    }
}

// ---------------------------------------------------------------------------
extern "C" void kernel_launch(void* const* d_in, const int* in_sizes, int n_in,
                              void* d_out, int out_size)
{
    const float* x  = (const float*)d_in[0];
    const float* wq = (const float*)d_in[1];
    const float* wk = (const float*)d_in[2];
    const float* wv = (const float*)d_in[3];
    const float* wo = (const float*)d_in[4];
    float* out = (float*)d_out;

    unsigned *xh, *xl, *wh, *wl;
    cudaGetSymbolAddress((void**)&xh, g_Xh);
    cudaGetSymbolAddress((void**)&xl, g_Xl);
    cudaGetSymbolAddress((void**)&wh, g_Wh);
    cudaGetSymbolAddress((void**)&wl, g_Wl);

    cudaFuncSetAttribute(qkv_gemm,  cudaFuncAttributeMaxDynamicSharedMemorySize, GEMM_SMEM_BYTES);
    cudaFuncSetAttribute(proj_gemm, cudaFuncAttributeMaxDynamicSharedMemorySize, GEMM_SMEM_BYTES);
    cudaFuncSetAttribute(attn_fwd,  cudaFuncAttributeMaxDynamicSharedMemorySize, ATTN_SMEM_BYTES);

    const int XW = MROWS * WPR;            // 2,097,152 words
    const int WW = D_MODEL * WPR;          //   524,288 words
    split_pack<<<XW / 256, 256>>>(x,  xh, xl, XW);
    split_pack<<<WW / 256, 256>>>(wq, wh + 0*(size_t)WW, wl + 0*(size_t)WW, WW);
    split_pack<<<WW / 256, 256>>>(wk, wh + 1*(size_t)WW, wl + 1*(size_t)WW, WW);
    split_pack<<<WW / 256, 256>>>(wv, wh + 2*(size_t)WW, wl + 2*(size_t)WW, WW);
    split_pack<<<WW / 256, 256>>>(wo, wh + 3*(size_t)WW, wl + 3*(size_t)WW, WW);

    dim3 gq(D_MODEL / 128, MROWS / 128, 3);          // (8,32,3)
    qkv_gemm<<<gq, 256, GEMM_SMEM_BYTES>>>();

    vtrans<<<dim3(SEQ / 128, NHEADS, BATCH), 256>>>();

    attn_fwd<<<dim3(SEQ / 128, NHEADS, BATCH), 256, ATTN_SMEM_BYTES>>>();

    dim3 gp(D_MODEL / 128, MROWS / 128);             // (8,32)
    proj_gemm<<<gp, 256, GEMM_SMEM_BYTES>>>(out);
}

// round 14
// speedup vs baseline: 1.0949x; 1.0949x over previous
#include <cuda_runtime.h>
#include <cuda_bf16.h>

#define D_MODEL 1024
#define NHEADS  16
#define DK      64
#define BATCH   2
#define SEQ     2048
#define MROWS   (BATCH*SEQ)   // 4096

// ---------------------------------------------------------------------------
// Scratch (device globals; allocation-free per harness rules).
// Q/K packed bf16x2 hi/lo: [b][h][s][32 words of dk-pairs]
// Vt packed bf16x2 hi/lo, transposed: [b][h][dk][1024 words of s-pairs]
__device__ unsigned g_Qh[(size_t)BATCH*NHEADS*SEQ*32];
__device__ unsigned g_Ql[(size_t)BATCH*NHEADS*SEQ*32];
__device__ unsigned g_Kh[(size_t)BATCH*NHEADS*SEQ*32];
__device__ unsigned g_Kl[(size_t)BATCH*NHEADS*SEQ*32];
__device__ float    g_V [(size_t)MROWS*D_MODEL];
__device__ unsigned g_Vth[(size_t)BATCH*NHEADS*DK*(SEQ/2)];
__device__ unsigned g_Vtl[(size_t)BATCH*NHEADS*DK*(SEQ/2)];
__device__ float    g_O [(size_t)MROWS*D_MODEL];

// ---------------------------------------------------------------------------
__device__ __forceinline__ float ex2f(float x) {
    float r; asm("ex2.approx.f32 %0, %1;" : "=f"(r) : "f"(x)); return r;
}
__device__ __forceinline__ unsigned pack2(float x, float y) {
    __nv_bfloat162 h = __floats2bfloat162_rn(x, y);
    return reinterpret_cast<unsigned&>(h);
}
__device__ __forceinline__ void split2(float x, float y, unsigned& hi, unsigned& lo) {
    __nv_bfloat162 h = __floats2bfloat162_rn(x, y);
    float xr = x - __bfloat162float(h.x);
    float yr = y - __bfloat162float(h.y);
    hi = reinterpret_cast<unsigned&>(h);
    lo = pack2(xr, yr);
}
__device__ __forceinline__ void mma_bf16(float* c, const unsigned* a, const unsigned* b) {
    asm volatile(
        "mma.sync.aligned.m16n8k16.row.col.f32.bf16.bf16.f32 "
        "{%0,%1,%2,%3}, {%4,%5,%6,%7}, {%8,%9}, {%0,%1,%2,%3};\n"
        : "+f"(c[0]), "+f"(c[1]), "+f"(c[2]), "+f"(c[3])
        : "r"(a[0]), "r"(a[1]), "r"(a[2]), "r"(a[3]), "r"(b[0]), "r"(b[1]));
}
__device__ __forceinline__ void ldsm4(unsigned* r, unsigned addr) {
    asm volatile("ldmatrix.sync.aligned.m8n8.x4.shared.b16 {%0,%1,%2,%3}, [%4];"
                 : "=r"(r[0]), "=r"(r[1]), "=r"(r[2]), "=r"(r[3]) : "r"(addr));
}
__device__ __forceinline__ unsigned ldsm_a_off(int lane, int stride_words) {
    int row = lane & 15;
    int wrd = (lane >> 4) * 4;
    return (unsigned)((row * stride_words + wrd) * 4);
}
__device__ __forceinline__ unsigned ldsm_b_off(int lane, int stride_words) {
    int jm  = lane & 7;
    int sel = lane >> 3;                 // 0..3
    int row = ((sel >> 1) << 3) + jm;    // 0..7 or 8..15
    int wrd = (sel & 1) * 4;
    return (unsigned)((row * stride_words + wrd) * 4);
}
__device__ __forceinline__ void cpa16(unsigned dst, const unsigned* src) {
    asm volatile("cp.async.cg.shared.global [%0], [%1], 16;\n" :: "r"(dst), "l"(src) : "memory");
}
__device__ __forceinline__ void cpa_commit() { asm volatile("cp.async.commit_group;\n" ::: "memory"); }
__device__ __forceinline__ void cpa_wait0()  { asm volatile("cp.async.wait_group 0;\n" ::: "memory"); }

// ---------------------------------------------------------------------------
// bf16x3 GEMM: C[128x128] = A[128x1024] * B[128x1024]^T, BK=16.
// 256 threads = 8 warps (2My x 4Nx), warp tile 64x32. 2 CTAs/SM.
// Fragment loads via ldmatrix.x4; loader stores via STS.128 (4 per thread).
// ---------------------------------------------------------------------------
#define AW 12
#define GSEG (128*AW)                         // words per tile array per stage
#define GEMM_SMEM_BYTES (8 * GSEG * 4)        // 2 stages x 4 arrays = 49152 B

__device__ __forceinline__ void gemm_main(const float* __restrict__ Ab,
                                          const float* __restrict__ Bb,
                                          float (&c)[4][4][4], unsigned* sm)
{
    unsigned* Ash = sm;                // [2][GSEG]
    unsigned* Asl = sm + 2*GSEG;
    unsigned* Bsh = sm + 4*GSEG;
    unsigned* Bsl = sm + 6*GSEG;
    const unsigned smb = (unsigned)__cvta_generic_to_shared(sm);

    const int tid  = threadIdx.x;
    const int warp = tid >> 5, lane = tid & 31;
    const int wy = warp >> 2;          // 0..1 (M)
    const int wx = warp & 3;           // 0..3 (N)
    const int pr = tid >> 1;           // loader row 0..127
    const int pc = (tid & 1) * 8;      // float offset 0 or 8
    const int pw = (tid & 1) * 4;      // word offset 0 or 4

    const unsigned aoff = ldsm_a_off(lane, AW);
    const unsigned boff = ldsm_b_off(lane, AW);

#pragma unroll
    for (int mi = 0; mi < 4; mi++)
#pragma unroll
        for (int ni = 0; ni < 4; ni++)
#pragma unroll
            for (int r = 0; r < 4; r++) c[mi][ni][r] = 0.f;

    // store one row-half (8 floats = 2 float4) split into hi/lo STS.128 pairs
    auto store_half = [&](unsigned* Dh, unsigned* Dl, float4 v0, float4 v1) {
        unsigned h0, l0, h1, l1, h2, l2, h3, l3;
        split2(v0.x, v0.y, h0, l0); split2(v0.z, v0.w, h1, l1);
        split2(v1.x, v1.y, h2, l2); split2(v1.z, v1.w, h3, l3);
        *(uint4*)(Dh + pr*AW + pw) = make_uint4(h0, h1, h2, h3);
        *(uint4*)(Dl + pr*AW + pw) = make_uint4(l0, l1, l2, l3);
    };

    // prologue: k-tile 0 -> stage 0
    {
        float4 a0 = *(const float4*)(Ab + (size_t)pr * 1024 + pc);
        float4 a1 = *(const float4*)(Ab + (size_t)pr * 1024 + pc + 4);
        float4 b0 = *(const float4*)(Bb + (size_t)pr * 1024 + pc);
        float4 b1 = *(const float4*)(Bb + (size_t)pr * 1024 + pc + 4);
        store_half(Ash, Asl, a0, a1);
        store_half(Bsh, Bsl, b0, b1);
    }
    __syncthreads();

    for (int kk = 0; kk < 1024; kk += 16) {
        const int buf = (kk >> 4) & 1;
        const bool pf = (kk + 16) < 1024;
        const unsigned AhB = smb + (unsigned)((0 + buf) * GSEG * 4);
        const unsigned AlB = smb + (unsigned)((2 + buf) * GSEG * 4);
        const unsigned BhB = smb + (unsigned)((4 + buf) * GSEG * 4);
        const unsigned BlB = smb + (unsigned)((6 + buf) * GSEG * 4);

        float4 na0, na1, nb0, nb1;
        if (pf) {
            na0 = *(const float4*)(Ab + (size_t)pr * 1024 + kk + 16 + pc);
            na1 = *(const float4*)(Ab + (size_t)pr * 1024 + kk + 16 + pc + 4);
            nb0 = *(const float4*)(Bb + (size_t)pr * 1024 + kk + 16 + pc);
            nb1 = *(const float4*)(Bb + (size_t)pr * 1024 + kk + 16 + pc + 4);
        }

        unsigned bh[4][2], bl[4][2];
#pragma unroll
        for (int p = 0; p < 2; p++) {
            const unsigned nbase = (unsigned)((wx * 32 + p * 16) * AW * 4);
            unsigned r4[4];
            ldsm4(r4, BhB + nbase + boff);
            bh[2*p][0] = r4[0]; bh[2*p][1] = r4[1];
            bh[2*p+1][0] = r4[2]; bh[2*p+1][1] = r4[3];
            ldsm4(r4, BlB + nbase + boff);
            bl[2*p][0] = r4[0]; bl[2*p][1] = r4[1];
            bl[2*p+1][0] = r4[2]; bl[2*p+1][1] = r4[3];
        }
#pragma unroll
        for (int mi = 0; mi < 4; mi++) {
            const unsigned rbase = (unsigned)((wy * 64 + mi * 16) * AW * 4);
            unsigned ah[4], al[4];
            ldsm4(ah, AhB + rbase + aoff);
            ldsm4(al, AlB + rbase + aoff);
#pragma unroll
            for (int ni = 0; ni < 4; ni++) mma_bf16(c[mi][ni], ah, bh[ni]);
#pragma unroll
            for (int ni = 0; ni < 4; ni++) mma_bf16(c[mi][ni], ah, bl[ni]);
#pragma unroll
            for (int ni = 0; ni < 4; ni++) mma_bf16(c[mi][ni], al, bh[ni]);
        }

        if (pf) {
            const int nb = buf ^ 1;
            store_half(Ash + nb*GSEG, Asl + nb*GSEG, na0, na1);
            store_half(Bsh + nb*GSEG, Bsl + nb*GSEG, nb0, nb1);
        }
        __syncthreads();
    }
}

// z=0 -> Q packed (prescaled), z=1 -> K packed, z=2 -> V f32
__global__ __launch_bounds__(256, 2)
void qkv_gemm(const float* __restrict__ X, const float* __restrict__ Wq,
              const float* __restrict__ Wk, const float* __restrict__ Wv)
{
    extern __shared__ unsigned gsm[];
    const int z = blockIdx.z;
    const float* Bm = (z == 0) ? Wq : (z == 1) ? Wk : Wv;
    const float* Ab = X  + (size_t)blockIdx.y * 128 * 1024;
    const float* Bb = Bm + (size_t)blockIdx.x * 128 * 1024;

    float c[4][4][4];
    gemm_main(Ab, Bb, c, gsm);

    const int tid  = threadIdx.x;
    const int warp = tid >> 5, lane = tid & 31;
    const int g = lane >> 2, t = lane & 3;
    const int wy = warp >> 2, wx = warp & 3;

    if (z < 2) {
        unsigned* Ph = z ? g_Kh : g_Qh;
        unsigned* Pl = z ? g_Kl : g_Ql;
        const float scale = z ? 1.f : 0.125f * 1.4426950408889634f;
#pragma unroll
        for (int mi = 0; mi < 4; mi++) {
            int row = blockIdx.y * 128 + wy * 64 + mi * 16 + g;
            int bb = row >> 11, s = row & 2047;
#pragma unroll
            for (int ni = 0; ni < 4; ni++) {
                int col = blockIdx.x * 128 + wx * 32 + ni * 8 + 2 * t;
                int hh = col >> 6, dkw = (col & 63) >> 1;
                size_t w = (((size_t)bb * NHEADS + hh) * SEQ + s) * 32 + dkw;
                unsigned hi, lo;
                split2(c[mi][ni][0] * scale, c[mi][ni][1] * scale, hi, lo);
                Ph[w] = hi; Pl[w] = lo;
                split2(c[mi][ni][2] * scale, c[mi][ni][3] * scale, hi, lo);
                Ph[w + 8*32] = hi; Pl[w + 8*32] = lo;
            }
        }
    } else {
#pragma unroll
        for (int mi = 0; mi < 4; mi++) {
            int row = blockIdx.y * 128 + wy * 64 + mi * 16 + g;
#pragma unroll
            for (int ni = 0; ni < 4; ni++) {
                int col = blockIdx.x * 128 + wx * 32 + ni * 8 + 2 * t;
                *(float2*)&g_V[(size_t)row * 1024 + col] =
                    make_float2(c[mi][ni][0], c[mi][ni][1]);
                *(float2*)&g_V[(size_t)(row + 8) * 1024 + col] =
                    make_float2(c[mi][ni][2], c[mi][ni][3]);
            }
        }
    }
}

__global__ __launch_bounds__(256, 2)
void proj_gemm(const float* __restrict__ Wo, float* __restrict__ Out)
{
    extern __shared__ unsigned gsm[];
    const float* Ab = g_O + (size_t)blockIdx.y * 128 * 1024;
    const float* Bb = Wo  + (size_t)blockIdx.x * 128 * 1024;

    float c[4][4][4];
    gemm_main(Ab, Bb, c, gsm);

    const int tid  = threadIdx.x;
    const int warp = tid >> 5, lane = tid & 31;
    const int g = lane >> 2, t = lane & 3;
    const int wy = warp >> 2, wx = warp & 3;
#pragma unroll
    for (int mi = 0; mi < 4; mi++) {
        int row = blockIdx.y * 128 + wy * 64 + mi * 16 + g;
#pragma unroll
        for (int ni = 0; ni < 4; ni++) {
            int col = blockIdx.x * 128 + wx * 32 + ni * 8 + 2 * t;
            *(float2*)&Out[(size_t)row * 1024 + col] =
                make_float2(c[mi][ni][0], c[mi][ni][1]);
            *(float2*)&Out[(size_t)(row + 8) * 1024 + col] =
                make_float2(c[mi][ni][2], c[mi][ni][3]);
        }
    }
}

// V transpose + split: g_V [b,s,h*64+dk] -> g_Vt{h,l} [b,h][dk][s/2 words]
__global__ __launch_bounds__(256)
void vtrans()
{
    __shared__ float smv[128 * 65];
    const int sc = blockIdx.x, h = blockIdx.y, b = blockIdx.z;
    const int tid = threadIdx.x;
    const float* src = g_V + ((size_t)b * SEQ + sc * 128) * D_MODEL + h * DK;
#pragma unroll
    for (int l = 0; l < 8; l++) {
        int idx = tid + l * 256;
        int r = idx >> 4, cc = (idx & 15) * 4;
        float4 v = *(const float4*)(src + (size_t)r * D_MODEL + cc);
        smv[r*65 + cc] = v.x; smv[r*65 + cc + 1] = v.y;
        smv[r*65 + cc + 2] = v.z; smv[r*65 + cc + 3] = v.w;
    }
    __syncthreads();
    const size_t dbase = ((size_t)(b * NHEADS + h) * DK) * 1024 + sc * 64;
#pragma unroll
    for (int l = 0; l < 16; l++) {
        int idx = tid + l * 256;
        int dk = idx >> 6, sw = idx & 63;
        unsigned hi, lo;
        split2(smv[(2*sw) * 65 + dk], smv[(2*sw + 1) * 65 + dk], hi, lo);
        g_Vth[dbase + (size_t)dk * 1024 + sw] = hi;
        g_Vtl[dbase + (size_t)dk * 1024 + sw] = lo;
    }
}

// ---------------------------------------------------------------------------
// Flash attention, bf16x3, cp.async double-buffered K/V, P in registers,
// ldmatrix fragment loads. (unchanged from R12 — best passing config)
// ---------------------------------------------------------------------------
#define KWS 36
#define VWS 68
#define ATTN_SMEM_BYTES ((2*128*KWS*2 + 2*64*VWS*2) * 4)   // 143360

__global__ __launch_bounds__(256, 1)
void attn_fwd()
{
    extern __shared__ unsigned sm[];
    const unsigned smb  = (unsigned)__cvta_generic_to_shared(sm);
    const unsigned KshB = smb;
    const unsigned KslB = smb + 2*128*KWS*4;
    const unsigned VshB = KslB + 2*128*KWS*4;
    const unsigned VslB = VshB + 2*64*VWS*4;

    const int qb = (gridDim.x - 1) - blockIdx.x;
    const int bh = blockIdx.z * NHEADS + blockIdx.y;
    const int tid = threadIdx.x, warp = tid >> 5, lane = tid & 31;
    const int g = lane >> 2, t = lane & 3;
    const int kr0 = tid >> 3, kch = (tid & 7) * 4;
    const int vd0 = tid >> 4, vch = (tid & 15) * 4;

    const unsigned boffK = ldsm_b_off(lane, KWS);
    const unsigned boffV = ldsm_b_off(lane, VWS);

    auto load_kv = [&](int buf, int j) {
        const size_t kbase = ((size_t)bh * SEQ + (size_t)j * 128) * 32;
#pragma unroll
        for (int l = 0; l < 4; l++) {
            int r = kr0 + l * 32;
            unsigned doff = (unsigned)((r * KWS + kch) * 4);
            cpa16(KshB + buf*(128*KWS*4) + doff, g_Kh + kbase + r*32 + kch);
            cpa16(KslB + buf*(128*KWS*4) + doff, g_Kl + kbase + r*32 + kch);
        }
        const size_t vbase = (size_t)bh * DK * 1024 + (size_t)j * 64;
#pragma unroll
        for (int l = 0; l < 4; l++) {
            int dk = vd0 + l * 16;
            unsigned doff = (unsigned)((dk * VWS + vch) * 4);
            cpa16(VshB + buf*(64*VWS*4) + doff, g_Vth + vbase + (size_t)dk*1024 + vch);
            cpa16(VslB + buf*(64*VWS*4) + doff, g_Vtl + vbase + (size_t)dk*1024 + vch);
        }
        cpa_commit();
    };

    load_kv(0, 0);

    unsigned qh[4][4], ql[4][4];
    {
        const size_t qbase = ((size_t)bh * SEQ + (size_t)qb * 128 + warp * 16 + g) * 32;
#pragma unroll
        for (int kt = 0; kt < 4; kt++) {
            qh[kt][0] = g_Qh[qbase + kt*8 + t];
            qh[kt][1] = g_Qh[qbase + 8*32 + kt*8 + t];
            qh[kt][2] = g_Qh[qbase + kt*8 + 4 + t];
            qh[kt][3] = g_Qh[qbase + 8*32 + kt*8 + 4 + t];
            ql[kt][0] = g_Ql[qbase + kt*8 + t];
            ql[kt][1] = g_Ql[qbase + 8*32 + kt*8 + t];
            ql[kt][2] = g_Ql[qbase + kt*8 + 4 + t];
            ql[kt][3] = g_Ql[qbase + 8*32 + kt*8 + 4 + t];
        }
    }

    float m0 = -1e30f, m1 = -1e30f, l0 = 0.f, l1 = 0.f;
    float o[8][4];
#pragma unroll
    for (int ni = 0; ni < 8; ni++)
#pragma unroll
        for (int r = 0; r < 4; r++) o[ni][r] = 0.f;

    const int prow0 = warp * 16 + g;
    const int prow1 = prow0 + 8;

    cpa_wait0();
    __syncthreads();

    int buf = 0;
    for (int j = 0; j <= qb; j++) {
        if (j < qb) load_kv(buf ^ 1, j + 1);

        const unsigned KhB_t = KshB + (unsigned)(buf * 128*KWS*4);
        const unsigned KlB_t = KslB + (unsigned)(buf * 128*KWS*4);
        const unsigned VhB_t = VshB + (unsigned)(buf * 64*VWS*4);
        const unsigned VlB_t = VslB + (unsigned)(buf * 64*VWS*4);

        float s[16][4];
#pragma unroll
        for (int ni = 0; ni < 16; ni++) {
            s[ni][0] = 0.f; s[ni][1] = 0.f; s[ni][2] = 0.f; s[ni][3] = 0.f;
        }
#pragma unroll
        for (int kt = 0; kt < 4; kt++) {
#pragma unroll
            for (int p = 0; p < 8; p++) {
                unsigned nb = (unsigned)(p * 16 * KWS * 4) + (unsigned)(kt * 32);
                unsigned kh[4], kl[4];
                ldsm4(kh, KhB_t + nb + boffK);
                ldsm4(kl, KlB_t + nb + boffK);
                mma_bf16(s[2*p],   qh[kt], kh);
                mma_bf16(s[2*p],   qh[kt], kl);
                mma_bf16(s[2*p],   ql[kt], kh);
                mma_bf16(s[2*p+1], qh[kt], kh + 2);
                mma_bf16(s[2*p+1], qh[kt], kl + 2);
                mma_bf16(s[2*p+1], ql[kt], kh + 2);
            }
        }

        if (j == qb) {
#pragma unroll
            for (int ni = 0; ni < 16; ni++) {
                int cb = ni * 8 + 2 * t;
                if (cb     > prow0) s[ni][0] = -1e30f;
                if (cb + 1 > prow0) s[ni][1] = -1e30f;
                if (cb     > prow1) s[ni][2] = -1e30f;
                if (cb + 1 > prow1) s[ni][3] = -1e30f;
            }
        }

        float rm0 = -1e30f, rm1 = -1e30f;
#pragma unroll
        for (int ni = 0; ni < 16; ni++) {
            rm0 = fmaxf(rm0, fmaxf(s[ni][0], s[ni][1]));
            rm1 = fmaxf(rm1, fmaxf(s[ni][2], s[ni][3]));
        }
        rm0 = fmaxf(rm0, __shfl_xor_sync(0xffffffffu, rm0, 1));
        rm0 = fmaxf(rm0, __shfl_xor_sync(0xffffffffu, rm0, 2));
        rm1 = fmaxf(rm1, __shfl_xor_sync(0xffffffffu, rm1, 1));
        rm1 = fmaxf(rm1, __shfl_xor_sync(0xffffffffu, rm1, 2));

        float mn0 = fmaxf(m0, rm0), mn1 = fmaxf(m1, rm1);
        float a0 = ex2f(m0 - mn0), a1 = ex2f(m1 - mn1);
        float rs0 = 0.f, rs1 = 0.f;
#pragma unroll
        for (int ni = 0; ni < 16; ni++) {
            s[ni][0] = ex2f(s[ni][0] - mn0);
            s[ni][1] = ex2f(s[ni][1] - mn0);
            s[ni][2] = ex2f(s[ni][2] - mn1);
            s[ni][3] = ex2f(s[ni][3] - mn1);
            rs0 += s[ni][0] + s[ni][1];
            rs1 += s[ni][2] + s[ni][3];
        }
        rs0 += __shfl_xor_sync(0xffffffffu, rs0, 1);
        rs0 += __shfl_xor_sync(0xffffffffu, rs0, 2);
        rs1 += __shfl_xor_sync(0xffffffffu, rs1, 1);
        rs1 += __shfl_xor_sync(0xffffffffu, rs1, 2);
        l0 = l0 * a0 + rs0;  m0 = mn0;
        l1 = l1 * a1 + rs1;  m1 = mn1;
#pragma unroll
        for (int ni = 0; ni < 8; ni++) {
            o[ni][0] *= a0; o[ni][1] *= a0;
            o[ni][2] *= a1; o[ni][3] *= a1;
        }

#pragma unroll
        for (int kt = 0; kt < 8; kt++) {
            unsigned ph[4], pl[4];
            split2(s[2*kt][0],   s[2*kt][1],   ph[0], pl[0]);
            split2(s[2*kt][2],   s[2*kt][3],   ph[1], pl[1]);
            split2(s[2*kt+1][0], s[2*kt+1][1], ph[2], pl[2]);
            split2(s[2*kt+1][2], s[2*kt+1][3], ph[3], pl[3]);
#pragma unroll
            for (int p = 0; p < 4; p++) {
                unsigned nb = (unsigned)(p * 16 * VWS * 4) + (unsigned)(kt * 32);
                unsigned vh[4], vl[4];
                ldsm4(vh, VhB_t + nb + boffV);
                ldsm4(vl, VlB_t + nb + boffV);
                mma_bf16(o[2*p],   ph, vh);
                mma_bf16(o[2*p],   ph, vl);
                mma_bf16(o[2*p],   pl, vh);
                mma_bf16(o[2*p+1], ph, vh + 2);
                mma_bf16(o[2*p+1], ph, vl + 2);
                mma_bf16(o[2*p+1], pl, vh + 2);
            }
        }

        if (j < qb) cpa_wait0();
        __syncthreads();
        buf ^= 1;
    }

    float inv0 = 1.f / l0, inv1 = 1.f / l1;
    const size_t obase = ((size_t)blockIdx.z * SEQ + (size_t)qb * 128) * D_MODEL
                       + blockIdx.y * DK;
#pragma unroll
    for (int ni = 0; ni < 8; ni++) {
        int col = ni * 8 + 2 * t;
        *(float2*)&g_O[obase + (size_t)prow0 * D_MODEL + col] =
            make_float2(o[ni][0] * inv0, o[ni][1] * inv0);
        *(float2*)&g_O[obase + (size_t)prow1 * D_MODEL + col] =
            make_float2(o[ni][2] * inv1, o[ni][3] * inv1);
    }
}

// ---------------------------------------------------------------------------
extern "C" void kernel_launch(void* const* d_in, const int* in_sizes, int n_in,
                              void* d_out, int out_size)
{
    const float* x  = (const float*)d_in[0];
    const float* wq = (const float*)d_in[1];
    const float* wk = (const float*)d_in[2];
    const float* wv = (const float*)d_in[3];
    const float* wo = (const float*)d_in[4];
    float* out = (float*)d_out;

    cudaFuncSetAttribute(qkv_gemm,  cudaFuncAttributeMaxDynamicSharedMemorySize, GEMM_SMEM_BYTES);
    cudaFuncSetAttribute(proj_gemm, cudaFuncAttributeMaxDynamicSharedMemorySize, GEMM_SMEM_BYTES);
    cudaFuncSetAttribute(attn_fwd,  cudaFuncAttributeMaxDynamicSharedMemorySize, ATTN_SMEM_BYTES);

    dim3 gq(D_MODEL / 128, MROWS / 128, 3);          // (8,32,3)
    qkv_gemm<<<gq, 256, GEMM_SMEM_BYTES>>>(x, wq, wk, wv);

    vtrans<<<dim3(SEQ / 128, NHEADS, BATCH), 256>>>();

    attn_fwd<<<dim3(SEQ / 128, NHEADS, BATCH), 256, ATTN_SMEM_BYTES>>>();

    dim3 gp(D_MODEL / 128, MROWS / 128);             // (8,32)
    proj_gemm<<<gp, 256, GEMM_SMEM_BYTES>>>(wo, out);
}

// round 15
// speedup vs baseline: 1.1172x; 1.0204x over previous
#include <cuda_runtime.h>
#include <cuda_bf16.h>

#define D_MODEL 1024
#define NHEADS  16
#define DK      64
#define BATCH   2
#define SEQ     2048
#define MROWS   (BATCH*SEQ)   // 4096

// ---------------------------------------------------------------------------
// Scratch (device globals; allocation-free per harness rules).
// Q/K packed bf16x2 hi/lo: [b][h][s][32 words of dk-pairs]
// Vt packed bf16x2 hi/lo, transposed: [b][h][dk][1024 words of s-pairs]
__device__ unsigned g_Qh[(size_t)BATCH*NHEADS*SEQ*32];
__device__ unsigned g_Ql[(size_t)BATCH*NHEADS*SEQ*32];
__device__ unsigned g_Kh[(size_t)BATCH*NHEADS*SEQ*32];
__device__ unsigned g_Kl[(size_t)BATCH*NHEADS*SEQ*32];
__device__ float    g_V [(size_t)MROWS*D_MODEL];
__device__ unsigned g_Vth[(size_t)BATCH*NHEADS*DK*(SEQ/2)];
__device__ unsigned g_Vtl[(size_t)BATCH*NHEADS*DK*(SEQ/2)];
__device__ float    g_O [(size_t)MROWS*D_MODEL];

// ---------------------------------------------------------------------------
__device__ __forceinline__ float ex2f(float x) {
    float r; asm("ex2.approx.f32 %0, %1;" : "=f"(r) : "f"(x)); return r;
}
__device__ __forceinline__ unsigned pack2(float x, float y) {
    __nv_bfloat162 h = __floats2bfloat162_rn(x, y);
    return reinterpret_cast<unsigned&>(h);
}
__device__ __forceinline__ void split2(float x, float y, unsigned& hi, unsigned& lo) {
    __nv_bfloat162 h = __floats2bfloat162_rn(x, y);
    float xr = x - __bfloat162float(h.x);
    float yr = y - __bfloat162float(h.y);
    hi = reinterpret_cast<unsigned&>(h);
    lo = pack2(xr, yr);
}
__device__ __forceinline__ void mma_bf16(float* c, const unsigned* a, const unsigned* b) {
    asm volatile(
        "mma.sync.aligned.m16n8k16.row.col.f32.bf16.bf16.f32 "
        "{%0,%1,%2,%3}, {%4,%5,%6,%7}, {%8,%9}, {%0,%1,%2,%3};\n"
        : "+f"(c[0]), "+f"(c[1]), "+f"(c[2]), "+f"(c[3])
        : "r"(a[0]), "r"(a[1]), "r"(a[2]), "r"(a[3]), "r"(b[0]), "r"(b[1]));
}
__device__ __forceinline__ void ldsm4(unsigned* r, unsigned addr) {
    asm volatile("ldmatrix.sync.aligned.m8n8.x4.shared.b16 {%0,%1,%2,%3}, [%4];"
                 : "=r"(r[0]), "=r"(r[1]), "=r"(r[2]), "=r"(r[3]) : "r"(addr));
}
__device__ __forceinline__ unsigned ldsm_a_off(int lane, int stride_words) {
    int row = lane & 15;
    int wrd = (lane >> 4) * 4;
    return (unsigned)((row * stride_words + wrd) * 4);
}
__device__ __forceinline__ unsigned ldsm_b_off(int lane, int stride_words) {
    int jm  = lane & 7;
    int sel = lane >> 3;                 // 0..3
    int row = ((sel >> 1) << 3) + jm;    // 0..7 or 8..15
    int wrd = (sel & 1) * 4;
    return (unsigned)((row * stride_words + wrd) * 4);
}
__device__ __forceinline__ void cpa16(unsigned dst, const unsigned* src) {
    asm volatile("cp.async.cg.shared.global [%0], [%1], 16;\n" :: "r"(dst), "l"(src) : "memory");
}
__device__ __forceinline__ void cpa_commit() { asm volatile("cp.async.commit_group;\n" ::: "memory"); }
__device__ __forceinline__ void cpa_wait0()  { asm volatile("cp.async.wait_group 0;\n" ::: "memory"); }

// ---------------------------------------------------------------------------
// bf16x3 GEMM: C[128x128] = A[128x1024] * B[128x1024]^T, BK=16.
// 256 threads = 8 warps (2My x 4Nx), warp tile 64x32. 2 CTAs/SM.
// (byte-identical to Round 12 — best validated GEMM config)
// ---------------------------------------------------------------------------
#define AW 12
#define GSEG (128*AW)
#define GEMM_SMEM_BYTES (8 * GSEG * 4)        // 49152 B

__device__ __forceinline__ void gemm_main(const float* __restrict__ Ab,
                                          const float* __restrict__ Bb,
                                          float (&c)[4][4][4], unsigned* sm)
{
    unsigned* Ash = sm;
    unsigned* Asl = sm + 2*GSEG;
    unsigned* Bsh = sm + 4*GSEG;
    unsigned* Bsl = sm + 6*GSEG;
    const unsigned smb = (unsigned)__cvta_generic_to_shared(sm);

    const int tid  = threadIdx.x;
    const int warp = tid >> 5, lane = tid & 31;
    const int wy = warp >> 2;
    const int wx = warp & 3;
    const int lr = tid >> 2;
    const int lc = (tid & 3) * 4;
    const int lw = lc >> 1;

    const unsigned aoff = ldsm_a_off(lane, AW);
    const unsigned boff = ldsm_b_off(lane, AW);

#pragma unroll
    for (int mi = 0; mi < 4; mi++)
#pragma unroll
        for (int ni = 0; ni < 4; ni++)
#pragma unroll
            for (int r = 0; r < 4; r++) c[mi][ni][r] = 0.f;

#pragma unroll
    for (int l = 0; l < 2; l++) {
        int r = lr + l * 64;
        float4 va = *(const float4*)(Ab + (size_t)r * 1024 + lc);
        unsigned h0, l0, h1, l1;
        split2(va.x, va.y, h0, l0); split2(va.z, va.w, h1, l1);
        Ash[r*AW + lw] = h0; Ash[r*AW + lw + 1] = h1;
        Asl[r*AW + lw] = l0; Asl[r*AW + lw + 1] = l1;
        float4 vb = *(const float4*)(Bb + (size_t)r * 1024 + lc);
        split2(vb.x, vb.y, h0, l0); split2(vb.z, vb.w, h1, l1);
        Bsh[r*AW + lw] = h0; Bsh[r*AW + lw + 1] = h1;
        Bsl[r*AW + lw] = l0; Bsl[r*AW + lw + 1] = l1;
    }
    __syncthreads();

    for (int kk = 0; kk < 1024; kk += 16) {
        const int buf = (kk >> 4) & 1;
        const bool pf = (kk + 16) < 1024;
        const unsigned AhB = smb + (unsigned)((0 + buf) * GSEG * 4);
        const unsigned AlB = smb + (unsigned)((2 + buf) * GSEG * 4);
        const unsigned BhB = smb + (unsigned)((4 + buf) * GSEG * 4);
        const unsigned BlB = smb + (unsigned)((6 + buf) * GSEG * 4);

        float4 nva[2], nvb[2];
        if (pf) {
#pragma unroll
            for (int l = 0; l < 2; l++) {
                int r = lr + l * 64;
                nva[l] = *(const float4*)(Ab + (size_t)r * 1024 + kk + 16 + lc);
                nvb[l] = *(const float4*)(Bb + (size_t)r * 1024 + kk + 16 + lc);
            }
        }

        unsigned bh[4][2], bl[4][2];
#pragma unroll
        for (int p = 0; p < 2; p++) {
            const unsigned nbase = (unsigned)((wx * 32 + p * 16) * AW * 4);
            unsigned r4[4];
            ldsm4(r4, BhB + nbase + boff);
            bh[2*p][0] = r4[0]; bh[2*p][1] = r4[1];
            bh[2*p+1][0] = r4[2]; bh[2*p+1][1] = r4[3];
            ldsm4(r4, BlB + nbase + boff);
            bl[2*p][0] = r4[0]; bl[2*p][1] = r4[1];
            bl[2*p+1][0] = r4[2]; bl[2*p+1][1] = r4[3];
        }
#pragma unroll
        for (int mi = 0; mi < 4; mi++) {
            const unsigned rbase = (unsigned)((wy * 64 + mi * 16) * AW * 4);
            unsigned ah[4], al[4];
            ldsm4(ah, AhB + rbase + aoff);
            ldsm4(al, AlB + rbase + aoff);
#pragma unroll
            for (int ni = 0; ni < 4; ni++) mma_bf16(c[mi][ni], ah, bh[ni]);
#pragma unroll
            for (int ni = 0; ni < 4; ni++) mma_bf16(c[mi][ni], ah, bl[ni]);
#pragma unroll
            for (int ni = 0; ni < 4; ni++) mma_bf16(c[mi][ni], al, bh[ni]);
        }

        if (pf) {
            const int nb = buf ^ 1;
            unsigned* nAh = Ash + nb * GSEG;  unsigned* nAl = Asl + nb * GSEG;
            unsigned* nBh = Bsh + nb * GSEG;  unsigned* nBl = Bsl + nb * GSEG;
#pragma unroll
            for (int l = 0; l < 2; l++) {
                int r = lr + l * 64;
                unsigned h0, l0, h1, l1;
                split2(nva[l].x, nva[l].y, h0, l0); split2(nva[l].z, nva[l].w, h1, l1);
                nAh[r*AW + lw] = h0; nAh[r*AW + lw + 1] = h1;
                nAl[r*AW + lw] = l0; nAl[r*AW + lw + 1] = l1;
                split2(nvb[l].x, nvb[l].y, h0, l0); split2(nvb[l].z, nvb[l].w, h1, l1);
                nBh[r*AW + lw] = h0; nBh[r*AW + lw + 1] = h1;
                nBl[r*AW + lw] = l0; nBl[r*AW + lw + 1] = l1;
            }
        }
        __syncthreads();
    }
}

// z=0 -> Q packed (prescaled), z=1 -> K packed, z=2 -> V f32
__global__ __launch_bounds__(256, 2)
void qkv_gemm(const float* __restrict__ X, const float* __restrict__ Wq,
              const float* __restrict__ Wk, const float* __restrict__ Wv)
{
    extern __shared__ unsigned gsm[];
    const int z = blockIdx.z;
    const float* Bm = (z == 0) ? Wq : (z == 1) ? Wk : Wv;
    const float* Ab = X  + (size_t)blockIdx.y * 128 * 1024;
    const float* Bb = Bm + (size_t)blockIdx.x * 128 * 1024;

    float c[4][4][4];
    gemm_main(Ab, Bb, c, gsm);

    const int tid  = threadIdx.x;
    const int warp = tid >> 5, lane = tid & 31;
    const int g = lane >> 2, t = lane & 3;
    const int wy = warp >> 2, wx = warp & 3;

    if (z < 2) {
        unsigned* Ph = z ? g_Kh : g_Qh;
        unsigned* Pl = z ? g_Kl : g_Ql;
        const float scale = z ? 1.f : 0.125f * 1.4426950408889634f;
#pragma unroll
        for (int mi = 0; mi < 4; mi++) {
            int row = blockIdx.y * 128 + wy * 64 + mi * 16 + g;
            int bb = row >> 11, s = row & 2047;
#pragma unroll
            for (int ni = 0; ni < 4; ni++) {
                int col = blockIdx.x * 128 + wx * 32 + ni * 8 + 2 * t;
                int hh = col >> 6, dkw = (col & 63) >> 1;
                size_t w = (((size_t)bb * NHEADS + hh) * SEQ + s) * 32 + dkw;
                unsigned hi, lo;
                split2(c[mi][ni][0] * scale, c[mi][ni][1] * scale, hi, lo);
                Ph[w] = hi; Pl[w] = lo;
                split2(c[mi][ni][2] * scale, c[mi][ni][3] * scale, hi, lo);
                Ph[w + 8*32] = hi; Pl[w + 8*32] = lo;
            }
        }
    } else {
#pragma unroll
        for (int mi = 0; mi < 4; mi++) {
            int row = blockIdx.y * 128 + wy * 64 + mi * 16 + g;
#pragma unroll
            for (int ni = 0; ni < 4; ni++) {
                int col = blockIdx.x * 128 + wx * 32 + ni * 8 + 2 * t;
                *(float2*)&g_V[(size_t)row * 1024 + col] =
                    make_float2(c[mi][ni][0], c[mi][ni][1]);
                *(float2*)&g_V[(size_t)(row + 8) * 1024 + col] =
                    make_float2(c[mi][ni][2], c[mi][ni][3]);
            }
        }
    }
}

__global__ __launch_bounds__(256, 2)
void proj_gemm(const float* __restrict__ Wo, float* __restrict__ Out)
{
    extern __shared__ unsigned gsm[];
    const float* Ab = g_O + (size_t)blockIdx.y * 128 * 1024;
    const float* Bb = Wo  + (size_t)blockIdx.x * 128 * 1024;

    float c[4][4][4];
    gemm_main(Ab, Bb, c, gsm);

    const int tid  = threadIdx.x;
    const int warp = tid >> 5, lane = tid & 31;
    const int g = lane >> 2, t = lane & 3;
    const int wy = warp >> 2, wx = warp & 3;
#pragma unroll
    for (int mi = 0; mi < 4; mi++) {
        int row = blockIdx.y * 128 + wy * 64 + mi * 16 + g;
#pragma unroll
        for (int ni = 0; ni < 4; ni++) {
            int col = blockIdx.x * 128 + wx * 32 + ni * 8 + 2 * t;
            *(float2*)&Out[(size_t)row * 1024 + col] =
                make_float2(c[mi][ni][0], c[mi][ni][1]);
            *(float2*)&Out[(size_t)(row + 8) * 1024 + col] =
                make_float2(c[mi][ni][2], c[mi][ni][3]);
        }
    }
}

// V transpose + split: g_V [b,s,h*64+dk] -> g_Vt{h,l} [b,h][dk][s/2 words]
__global__ __launch_bounds__(256)
void vtrans()
{
    __shared__ float smv[128 * 65];
    const int sc = blockIdx.x, h = blockIdx.y, b = blockIdx.z;
    const int tid = threadIdx.x;
    const float* src = g_V + ((size_t)b * SEQ + sc * 128) * D_MODEL + h * DK;
#pragma unroll
    for (int l = 0; l < 8; l++) {
        int idx = tid + l * 256;
        int r = idx >> 4, cc = (idx & 15) * 4;
        float4 v = *(const float4*)(src + (size_t)r * D_MODEL + cc);
        smv[r*65 + cc] = v.x; smv[r*65 + cc + 1] = v.y;
        smv[r*65 + cc + 2] = v.z; smv[r*65 + cc + 3] = v.w;
    }
    __syncthreads();
    const size_t dbase = ((size_t)(b * NHEADS + h) * DK) * 1024 + sc * 64;
#pragma unroll
    for (int l = 0; l < 16; l++) {
        int idx = tid + l * 256;
        int dk = idx >> 6, sw = idx & 63;
        unsigned hi, lo;
        split2(smv[(2*sw) * 65 + dk], smv[(2*sw + 1) * 65 + dk], hi, lo);
        g_Vth[dbase + (size_t)dk * 1024 + sw] = hi;
        g_Vtl[dbase + (size_t)dk * 1024 + sw] = lo;
    }
}

// ---------------------------------------------------------------------------
// Flash attention, bf16x3, Bc=64 KV tiles, 2 CTAs/SM, cp.async double-buffered,
// P in registers, ldmatrix fragment loads.
// ---------------------------------------------------------------------------
#define KWS 36
#define VWS 36
#define KTB (64*KWS*4)     // bytes per K tile array per buffer (9216)
#define VTB (64*VWS*4)     // bytes per V tile array per buffer (9216)
#define ATTN_SMEM_BYTES (4 * 2 * KTB)   // 73728

__global__ __launch_bounds__(256, 2)
void attn_fwd()
{
    extern __shared__ unsigned sm[];
    const unsigned smb  = (unsigned)__cvta_generic_to_shared(sm);
    const unsigned KshB = smb;
    const unsigned KslB = smb + 2*KTB;
    const unsigned VshB = smb + 4*KTB;
    const unsigned VslB = smb + 6*KTB;

    const int qb = (gridDim.x - 1) - blockIdx.x;   // heavy blocks first
    const int bh = blockIdx.z * NHEADS + blockIdx.y;
    const int tid = threadIdx.x, warp = tid >> 5, lane = tid & 31;
    const int g = lane >> 2, t = lane & 3;

    const unsigned boffK = ldsm_b_off(lane, KWS);
    const unsigned boffV = ldsm_b_off(lane, VWS);

    // loader: 64 rows x 8 chunks(16B) per array, 512 chunks over 256 threads
    auto load_kv = [&](int buf, int j) {
        const size_t kbase = ((size_t)bh * SEQ + (size_t)j * 64) * 32;
        const size_t vbase = (size_t)bh * DK * 1024 + (size_t)j * 32;
#pragma unroll
        for (int l = 0; l < 2; l++) {
            int idx = tid + l * 256;
            int r = idx >> 3, ch = (idx & 7) * 4;
            unsigned doff = (unsigned)((r * KWS + ch) * 4);
            cpa16(KshB + buf*KTB + doff, g_Kh + kbase + r*32 + ch);
            cpa16(KslB + buf*KTB + doff, g_Kl + kbase + r*32 + ch);
            unsigned voff = (unsigned)((r * VWS + ch) * 4);
            cpa16(VshB + buf*VTB + voff, g_Vth + vbase + (size_t)r*1024 + ch);
            cpa16(VslB + buf*VTB + voff, g_Vtl + vbase + (size_t)r*1024 + ch);
        }
        cpa_commit();
    };

    load_kv(0, 0);

    unsigned qh[4][4], ql[4][4];
    {
        const size_t qbase = ((size_t)bh * SEQ + (size_t)qb * 128 + warp * 16 + g) * 32;
#pragma unroll
        for (int kt = 0; kt < 4; kt++) {
            qh[kt][0] = g_Qh[qbase + kt*8 + t];
            qh[kt][1] = g_Qh[qbase + 8*32 + kt*8 + t];
            qh[kt][2] = g_Qh[qbase + kt*8 + 4 + t];
            qh[kt][3] = g_Qh[qbase + 8*32 + kt*8 + 4 + t];
            ql[kt][0] = g_Ql[qbase + kt*8 + t];
            ql[kt][1] = g_Ql[qbase + 8*32 + kt*8 + t];
            ql[kt][2] = g_Ql[qbase + kt*8 + 4 + t];
            ql[kt][3] = g_Ql[qbase + 8*32 + kt*8 + 4 + t];
        }
    }

    float m0 = -1e30f, m1 = -1e30f, l0 = 0.f, l1 = 0.f;
    float o[8][4];
#pragma unroll
    for (int ni = 0; ni < 8; ni++)
#pragma unroll
        for (int r = 0; r < 4; r++) o[ni][r] = 0.f;

    const int prow0 = warp * 16 + g;
    const int prow1 = prow0 + 8;
    const int NT = 2 * qb + 2;          // 64-col tiles this CTA touches

    cpa_wait0();
    __syncthreads();

    int buf = 0;
    for (int j = 0; j < NT; j++) {
        if (j + 1 < NT) load_kv(buf ^ 1, j + 1);

        const unsigned KhB_t = KshB + (unsigned)(buf * KTB);
        const unsigned KlB_t = KslB + (unsigned)(buf * KTB);
        const unsigned VhB_t = VshB + (unsigned)(buf * VTB);
        const unsigned VlB_t = VslB + (unsigned)(buf * VTB);

        // ---- S = Q*K^T : 8 n-tiles of 8 cols ----
        float s[8][4];
#pragma unroll
        for (int ni = 0; ni < 8; ni++) {
            s[ni][0] = 0.f; s[ni][1] = 0.f; s[ni][2] = 0.f; s[ni][3] = 0.f;
        }
#pragma unroll
        for (int kt = 0; kt < 4; kt++) {
#pragma unroll
            for (int p = 0; p < 4; p++) {
                unsigned nb = (unsigned)(p * 16 * KWS * 4) + (unsigned)(kt * 32);
                unsigned kh[4], kl[4];
                ldsm4(kh, KhB_t + nb + boffK);
                ldsm4(kl, KlB_t + nb + boffK);
                mma_bf16(s[2*p],   qh[kt], kh);
                mma_bf16(s[2*p],   qh[kt], kl);
                mma_bf16(s[2*p],   ql[kt], kh);
                mma_bf16(s[2*p+1], qh[kt], kh + 2);
                mma_bf16(s[2*p+1], qh[kt], kl + 2);
                mma_bf16(s[2*p+1], ql[kt], kh + 2);
            }
        }

        // causal mask: only the last two tiles (diagonal region) need it
        if (j >= 2 * qb) {
            const int cofs = (j - 2 * qb) * 64;
#pragma unroll
            for (int ni = 0; ni < 8; ni++) {
                int cb = cofs + ni * 8 + 2 * t;
                if (cb     > prow0) s[ni][0] = -1e30f;
                if (cb + 1 > prow0) s[ni][1] = -1e30f;
                if (cb     > prow1) s[ni][2] = -1e30f;
                if (cb + 1 > prow1) s[ni][3] = -1e30f;
            }
        }

        // ---- online softmax (exp2 domain), quad reduction ----
        float rm0 = -1e30f, rm1 = -1e30f;
#pragma unroll
        for (int ni = 0; ni < 8; ni++) {
            rm0 = fmaxf(rm0, fmaxf(s[ni][0], s[ni][1]));
            rm1 = fmaxf(rm1, fmaxf(s[ni][2], s[ni][3]));
        }
        rm0 = fmaxf(rm0, __shfl_xor_sync(0xffffffffu, rm0, 1));
        rm0 = fmaxf(rm0, __shfl_xor_sync(0xffffffffu, rm0, 2));
        rm1 = fmaxf(rm1, __shfl_xor_sync(0xffffffffu, rm1, 1));
        rm1 = fmaxf(rm1, __shfl_xor_sync(0xffffffffu, rm1, 2));

        float mn0 = fmaxf(m0, rm0), mn1 = fmaxf(m1, rm1);
        float a0 = ex2f(m0 - mn0), a1 = ex2f(m1 - mn1);
        float rs0 = 0.f, rs1 = 0.f;
#pragma unroll
        for (int ni = 0; ni < 8; ni++) {
            s[ni][0] = ex2f(s[ni][0] - mn0);
            s[ni][1] = ex2f(s[ni][1] - mn0);
            s[ni][2] = ex2f(s[ni][2] - mn1);
            s[ni][3] = ex2f(s[ni][3] - mn1);
            rs0 += s[ni][0] + s[ni][1];
            rs1 += s[ni][2] + s[ni][3];
        }
        rs0 += __shfl_xor_sync(0xffffffffu, rs0, 1);
        rs0 += __shfl_xor_sync(0xffffffffu, rs0, 2);
        rs1 += __shfl_xor_sync(0xffffffffu, rs1, 1);
        rs1 += __shfl_xor_sync(0xffffffffu, rs1, 2);
        l0 = l0 * a0 + rs0;  m0 = mn0;
        l1 = l1 * a1 + rs1;  m1 = mn1;
#pragma unroll
        for (int ni = 0; ni < 8; ni++) {
            o[ni][0] *= a0; o[ni][1] *= a0;
            o[ni][2] *= a1; o[ni][3] *= a1;
        }

        // ---- O += P*V : kt over 4 s-chunks, p over 4 dk-groups ----
#pragma unroll
        for (int kt = 0; kt < 4; kt++) {
            unsigned ph[4], pl[4];
            split2(s[2*kt][0],   s[2*kt][1],   ph[0], pl[0]);
            split2(s[2*kt][2],   s[2*kt][3],   ph[1], pl[1]);
            split2(s[2*kt+1][0], s[2*kt+1][1], ph[2], pl[2]);
            split2(s[2*kt+1][2], s[2*kt+1][3], ph[3], pl[3]);
#pragma unroll
            for (int p = 0; p < 4; p++) {
                unsigned nb = (unsigned)(p * 16 * VWS * 4) + (unsigned)(kt * 32);
                unsigned vh[4], vl[4];
                ldsm4(vh, VhB_t + nb + boffV);
                ldsm4(vl, VlB_t + nb + boffV);
                mma_bf16(o[2*p],   ph, vh);
                mma_bf16(o[2*p],   ph, vl);
                mma_bf16(o[2*p],   pl, vh);
                mma_bf16(o[2*p+1], ph, vh + 2);
                mma_bf16(o[2*p+1], ph, vl + 2);
                mma_bf16(o[2*p+1], pl, vh + 2);
            }
        }

        if (j + 1 < NT) cpa_wait0();
        __syncthreads();
        buf ^= 1;
    }

    float inv0 = 1.f / l0, inv1 = 1.f / l1;
    const size_t obase = ((size_t)blockIdx.z * SEQ + (size_t)qb * 128) * D_MODEL
                       + blockIdx.y * DK;
#pragma unroll
    for (int ni = 0; ni < 8; ni++) {
        int col = ni * 8 + 2 * t;
        *(float2*)&g_O[obase + (size_t)prow0 * D_MODEL + col] =
            make_float2(o[ni][0] * inv0, o[ni][1] * inv0);
        *(float2*)&g_O[obase + (size_t)prow1 * D_MODEL + col] =
            make_float2(o[ni][2] * inv1, o[ni][3] * inv1);
    }
}

// ---------------------------------------------------------------------------
extern "C" void kernel_launch(void* const* d_in, const int* in_sizes, int n_in,
                              void* d_out, int out_size)
{
    const float* x  = (const float*)d_in[0];
    const float* wq = (const float*)d_in[1];
    const float* wk = (const float*)d_in[2];
    const float* wv = (const float*)d_in[3];
    const float* wo = (const float*)d_in[4];
    float* out = (float*)d_out;

    cudaFuncSetAttribute(qkv_gemm,  cudaFuncAttributeMaxDynamicSharedMemorySize, GEMM_SMEM_BYTES);
    cudaFuncSetAttribute(proj_gemm, cudaFuncAttributeMaxDynamicSharedMemorySize, GEMM_SMEM_BYTES);
    cudaFuncSetAttribute(attn_fwd,  cudaFuncAttributeMaxDynamicSharedMemorySize, ATTN_SMEM_BYTES);

    dim3 gq(D_MODEL / 128, MROWS / 128, 3);          // (8,32,3)
    qkv_gemm<<<gq, 256, GEMM_SMEM_BYTES>>>(x, wq, wk, wv);

    vtrans<<<dim3(SEQ / 128, NHEADS, BATCH), 256>>>();

    attn_fwd<<<dim3(SEQ / 128, NHEADS, BATCH), 256, ATTN_SMEM_BYTES>>>();

    dim3 gp(D_MODEL / 128, MROWS / 128);             // (8,32)
    proj_gemm<<<gp, 256, GEMM_SMEM_BYTES>>>(wo, out);
}

// round 16
// speedup vs baseline: 1.1927x; 1.0676x over previous
#include <cuda_runtime.h>
#include <cuda_bf16.h>

#define D_MODEL 1024
#define NHEADS  16
#define DK      64
#define BATCH   2
#define SEQ     2048
#define MROWS   (BATCH*SEQ)   // 4096

// ---------------------------------------------------------------------------
// Scratch (device globals; allocation-free per harness rules).
// Tiled packed layout for GEMM operands: [rtile][kt=64][row=128][8 words],
// word = bf16x2. One rtile = 64*128*8 = 65536 words.
// ---------------------------------------------------------------------------
#define RTW 65536
__device__ unsigned g_Xth[(size_t)32*RTW];          // X tiled: 32 row-tiles
__device__ unsigned g_Xtl[(size_t)32*RTW];
__device__ unsigned g_Wth[(size_t)4*8*RTW];         // Wq,Wk,Wv,Wo x 8 row-tiles
__device__ unsigned g_Wtl[(size_t)4*8*RTW];
__device__ unsigned g_Oth[(size_t)32*RTW];          // attention O tiled
__device__ unsigned g_Otl[(size_t)32*RTW];
// attention-side packed tensors (unchanged from R12)
__device__ unsigned g_Qh[(size_t)BATCH*NHEADS*SEQ*32];
__device__ unsigned g_Ql[(size_t)BATCH*NHEADS*SEQ*32];
__device__ unsigned g_Kh[(size_t)BATCH*NHEADS*SEQ*32];
__device__ unsigned g_Kl[(size_t)BATCH*NHEADS*SEQ*32];
__device__ float    g_V [(size_t)MROWS*D_MODEL];
__device__ unsigned g_Vth[(size_t)BATCH*NHEADS*DK*(SEQ/2)];
__device__ unsigned g_Vtl[(size_t)BATCH*NHEADS*DK*(SEQ/2)];

// ---------------------------------------------------------------------------
__device__ __forceinline__ float ex2f(float x) {
    float r; asm("ex2.approx.f32 %0, %1;" : "=f"(r) : "f"(x)); return r;
}
__device__ __forceinline__ unsigned pack2(float x, float y) {
    __nv_bfloat162 h = __floats2bfloat162_rn(x, y);
    return reinterpret_cast<unsigned&>(h);
}
__device__ __forceinline__ void split2(float x, float y, unsigned& hi, unsigned& lo) {
    __nv_bfloat162 h = __floats2bfloat162_rn(x, y);
    float xr = x - __bfloat162float(h.x);
    float yr = y - __bfloat162float(h.y);
    hi = reinterpret_cast<unsigned&>(h);
    lo = pack2(xr, yr);
}
__device__ __forceinline__ void mma_bf16(float* c, const unsigned* a, const unsigned* b) {
    asm volatile(
        "mma.sync.aligned.m16n8k16.row.col.f32.bf16.bf16.f32 "
        "{%0,%1,%2,%3}, {%4,%5,%6,%7}, {%8,%9}, {%0,%1,%2,%3};\n"
        : "+f"(c[0]), "+f"(c[1]), "+f"(c[2]), "+f"(c[3])
        : "r"(a[0]), "r"(a[1]), "r"(a[2]), "r"(a[3]), "r"(b[0]), "r"(b[1]));
}
__device__ __forceinline__ void ldsm4(unsigned* r, unsigned addr) {
    asm volatile("ldmatrix.sync.aligned.m8n8.x4.shared.b16 {%0,%1,%2,%3}, [%4];"
                 : "=r"(r[0]), "=r"(r[1]), "=r"(r[2]), "=r"(r[3]) : "r"(addr));
}
__device__ __forceinline__ unsigned ldsm_a_off(int lane, int stride_words) {
    int row = lane & 15;
    int wrd = (lane >> 4) * 4;
    return (unsigned)((row * stride_words + wrd) * 4);
}
__device__ __forceinline__ unsigned ldsm_b_off(int lane, int stride_words) {
    int jm  = lane & 7;
    int sel = lane >> 3;
    int row = ((sel >> 1) << 3) + jm;
    int wrd = (sel & 1) * 4;
    return (unsigned)((row * stride_words + wrd) * 4);
}
// forced scalar shared stores (prevent STS.128 fusion -> R14 bank pattern)
__device__ __forceinline__ void sts4_scalar(unsigned addr, uint4 v) {
    asm volatile("st.shared.u32 [%0], %1;"      :: "r"(addr),      "r"(v.x) : "memory");
    asm volatile("st.shared.u32 [%0+4], %1;"    :: "r"(addr),      "r"(v.y) : "memory");
    asm volatile("st.shared.u32 [%0+8], %1;"    :: "r"(addr),      "r"(v.z) : "memory");
    asm volatile("st.shared.u32 [%0+12], %1;"   :: "r"(addr),      "r"(v.w) : "memory");
}
__device__ __forceinline__ void cpa16(unsigned dst, const unsigned* src) {
    asm volatile("cp.async.cg.shared.global [%0], [%1], 16;\n" :: "r"(dst), "l"(src) : "memory");
}
__device__ __forceinline__ void cpa_commit() { asm volatile("cp.async.commit_group;\n" ::: "memory"); }
__device__ __forceinline__ void cpa_wait0()  { asm volatile("cp.async.wait_group 0;\n" ::: "memory"); }

// ---------------------------------------------------------------------------
// Pack f32 [rtiles*128, 1024] row-major -> tiled packed hi/lo words.
// word w: w8=w&7, row=(w>>3)&127, kt=(w>>10)&63, rt=w>>16
// ---------------------------------------------------------------------------
__global__ void pack_tiled(const float* __restrict__ src, unsigned* __restrict__ dh,
                           unsigned* __restrict__ dl, int nwords)
{
    int w = blockIdx.x * 256 + threadIdx.x;
    if (w < nwords) {
        int w8 = w & 7, row = (w >> 3) & 127, kt = (w >> 10) & 63, rt = w >> 16;
        float2 v = *(const float2*)(src + ((size_t)(rt * 128 + row) * 1024) + kt * 16 + w8 * 2);
        unsigned hi, lo; split2(v.x, v.y, hi, lo);
        dh[w] = hi; dl[w] = lo;
    }
}

// ---------------------------------------------------------------------------
// bf16x3 GEMM on tiled pre-split operands: C[128x128], BK=16, 2 CTAs/SM.
// 256 threads = 8 warps (2My x 4Nx), warp tile 64x32.
// Loader: 4 coalesced LDG.128 + 16 forced STS.32 per thread per k-step.
// Smem layout identical to R12 (stride-12, conflict-free ldmatrix).
// ---------------------------------------------------------------------------
#define AW 12
#define GSEG (128*AW)
#define GEMM_SMEM_BYTES (8 * GSEG * 4)        // 49152 B

__device__ __forceinline__ void gemm_main(
    const unsigned* __restrict__ Ah_g, const unsigned* __restrict__ Al_g,
    const unsigned* __restrict__ Bh_g, const unsigned* __restrict__ Bl_g,
    float (&c)[4][4][4], unsigned* sm)
{
    const unsigned smb = (unsigned)__cvta_generic_to_shared(sm);
    const int tid  = threadIdx.x;
    const int warp = tid >> 5, lane = tid & 31;
    const int wy = warp >> 2;
    const int wx = warp & 3;
    const int prow = tid >> 1;            // 0..127
    const int phal = (tid & 1) * 4;       // word 0 or 4

    const unsigned aoff = ldsm_a_off(lane, AW);
    const unsigned boff = ldsm_b_off(lane, AW);
    const unsigned soff = (unsigned)((prow * AW + phal) * 4);   // smem byte offset

#pragma unroll
    for (int mi = 0; mi < 4; mi++)
#pragma unroll
        for (int ni = 0; ni < 4; ni++)
#pragma unroll
            for (int r = 0; r < 4; r++) c[mi][ni][r] = 0.f;

    // gmem chunk offset for k-step kt: tiled [kt][row][8w] -> linear tid*4 words
    auto ld4 = [&](int kt, uint4& ah, uint4& al, uint4& bh, uint4& bl) {
        const size_t o = (size_t)kt * 1024 + (size_t)tid * 4;
        ah = *(const uint4*)(Ah_g + o);
        al = *(const uint4*)(Al_g + o);
        bh = *(const uint4*)(Bh_g + o);
        bl = *(const uint4*)(Bl_g + o);
    };
    auto st4 = [&](int buf, uint4 ah, uint4 al, uint4 bh, uint4 bl) {
        const unsigned base = smb + (unsigned)(buf * GSEG * 4);
        sts4_scalar(base + soff,                       ah);
        sts4_scalar(base + (unsigned)(2*GSEG*4) + soff, al);
        sts4_scalar(base + (unsigned)(4*GSEG*4) + soff, bh);
        sts4_scalar(base + (unsigned)(6*GSEG*4) + soff, bl);
    };

    // prologue
    {
        uint4 ah, al, bh, bl;
        ld4(0, ah, al, bh, bl);
        st4(0, ah, al, bh, bl);
    }
    __syncthreads();

    for (int kt = 0; kt < 64; kt++) {
        const int buf = kt & 1;
        const bool pf = (kt + 1) < 64;
        const unsigned AhB = smb + (unsigned)((0 + buf) * GSEG * 4);
        const unsigned AlB = smb + (unsigned)((2 + buf) * GSEG * 4);
        const unsigned BhB = smb + (unsigned)((4 + buf) * GSEG * 4);
        const unsigned BlB = smb + (unsigned)((6 + buf) * GSEG * 4);

        uint4 nah, nal, nbh, nbl;
        if (pf) ld4(kt + 1, nah, nal, nbh, nbl);

        unsigned bh[4][2], bl[4][2];
#pragma unroll
        for (int p = 0; p < 2; p++) {
            const unsigned nbase = (unsigned)((wx * 32 + p * 16) * AW * 4);
            unsigned r4[4];
            ldsm4(r4, BhB + nbase + boff);
            bh[2*p][0] = r4[0]; bh[2*p][1] = r4[1];
            bh[2*p+1][0] = r4[2]; bh[2*p+1][1] = r4[3];
            ldsm4(r4, BlB + nbase + boff);
            bl[2*p][0] = r4[0]; bl[2*p][1] = r4[1];
            bl[2*p+1][0] = r4[2]; bl[2*p+1][1] = r4[3];
        }
#pragma unroll
        for (int mi = 0; mi < 4; mi++) {
            const unsigned rbase = (unsigned)((wy * 64 + mi * 16) * AW * 4);
            unsigned ah[4], al[4];
            ldsm4(ah, AhB + rbase + aoff);
            ldsm4(al, AlB + rbase + aoff);
#pragma unroll
            for (int ni = 0; ni < 4; ni++) mma_bf16(c[mi][ni], ah, bh[ni]);
#pragma unroll
            for (int ni = 0; ni < 4; ni++) mma_bf16(c[mi][ni], ah, bl[ni]);
#pragma unroll
            for (int ni = 0; ni < 4; ni++) mma_bf16(c[mi][ni], al, bh[ni]);
        }

        if (pf) st4(buf ^ 1, nah, nal, nbh, nbl);
        __syncthreads();
    }
}

// z=0 -> Q packed (prescaled), z=1 -> K packed, z=2 -> V f32
__global__ __launch_bounds__(256, 2)
void qkv_gemm()
{
    extern __shared__ unsigned gsm[];
    const int z = blockIdx.z;
    const size_t aslot = (size_t)blockIdx.y * RTW;
    const size_t bslot = ((size_t)z * 8 + blockIdx.x) * RTW;

    float c[4][4][4];
    gemm_main(g_Xth + aslot, g_Xtl + aslot, g_Wth + bslot, g_Wtl + bslot, c, gsm);

    const int tid  = threadIdx.x;
    const int warp = tid >> 5, lane = tid & 31;
    const int g = lane >> 2, t = lane & 3;
    const int wy = warp >> 2, wx = warp & 3;

    if (z < 2) {
        unsigned* Ph = z ? g_Kh : g_Qh;
        unsigned* Pl = z ? g_Kl : g_Ql;
        const float scale = z ? 1.f : 0.125f * 1.4426950408889634f;
#pragma unroll
        for (int mi = 0; mi < 4; mi++) {
            int row = blockIdx.y * 128 + wy * 64 + mi * 16 + g;
            int bb = row >> 11, s = row & 2047;
#pragma unroll
            for (int ni = 0; ni < 4; ni++) {
                int col = blockIdx.x * 128 + wx * 32 + ni * 8 + 2 * t;
                int hh = col >> 6, dkw = (col & 63) >> 1;
                size_t w = (((size_t)bb * NHEADS + hh) * SEQ + s) * 32 + dkw;
                unsigned hi, lo;
                split2(c[mi][ni][0] * scale, c[mi][ni][1] * scale, hi, lo);
                Ph[w] = hi; Pl[w] = lo;
                split2(c[mi][ni][2] * scale, c[mi][ni][3] * scale, hi, lo);
                Ph[w + 8*32] = hi; Pl[w + 8*32] = lo;
            }
        }
    } else {
#pragma unroll
        for (int mi = 0; mi < 4; mi++) {
            int row = blockIdx.y * 128 + wy * 64 + mi * 16 + g;
#pragma unroll
            for (int ni = 0; ni < 4; ni++) {
                int col = blockIdx.x * 128 + wx * 32 + ni * 8 + 2 * t;
                *(float2*)&g_V[(size_t)row * 1024 + col] =
                    make_float2(c[mi][ni][0], c[mi][ni][1]);
                *(float2*)&g_V[(size_t)(row + 8) * 1024 + col] =
                    make_float2(c[mi][ni][2], c[mi][ni][3]);
            }
        }
    }
}

__global__ __launch_bounds__(256, 2)
void proj_gemm(float* __restrict__ Out)
{
    extern __shared__ unsigned gsm[];
    const size_t aslot = (size_t)blockIdx.y * RTW;
    const size_t bslot = ((size_t)3 * 8 + blockIdx.x) * RTW;

    float c[4][4][4];
    gemm_main(g_Oth + aslot, g_Otl + aslot, g_Wth + bslot, g_Wtl + bslot, c, gsm);

    const int tid  = threadIdx.x;
    const int warp = tid >> 5, lane = tid & 31;
    const int g = lane >> 2, t = lane & 3;
    const int wy = warp >> 2, wx = warp & 3;
#pragma unroll
    for (int mi = 0; mi < 4; mi++) {
        int row = blockIdx.y * 128 + wy * 64 + mi * 16 + g;
#pragma unroll
        for (int ni = 0; ni < 4; ni++) {
            int col = blockIdx.x * 128 + wx * 32 + ni * 8 + 2 * t;
            *(float2*)&Out[(size_t)row * 1024 + col] =
                make_float2(c[mi][ni][0], c[mi][ni][1]);
            *(float2*)&Out[(size_t)(row + 8) * 1024 + col] =
                make_float2(c[mi][ni][2], c[mi][ni][3]);
        }
    }
}

// V transpose + split: g_V [b,s,h*64+dk] -> g_Vt{h,l} [b,h][dk][s/2 words]
__global__ __launch_bounds__(256)
void vtrans()
{
    __shared__ float smv[128 * 65];
    const int sc = blockIdx.x, h = blockIdx.y, b = blockIdx.z;
    const int tid = threadIdx.x;
    const float* src = g_V + ((size_t)b * SEQ + sc * 128) * D_MODEL + h * DK;
#pragma unroll
    for (int l = 0; l < 8; l++) {
        int idx = tid + l * 256;
        int r = idx >> 4, cc = (idx & 15) * 4;
        float4 v = *(const float4*)(src + (size_t)r * D_MODEL + cc);
        smv[r*65 + cc] = v.x; smv[r*65 + cc + 1] = v.y;
        smv[r*65 + cc + 2] = v.z; smv[r*65 + cc + 3] = v.w;
    }
    __syncthreads();
    const size_t dbase = ((size_t)(b * NHEADS + h) * DK) * 1024 + sc * 64;
#pragma unroll
    for (int l = 0; l < 16; l++) {
        int idx = tid + l * 256;
        int dk = idx >> 6, sw = idx & 63;
        unsigned hi, lo;
        split2(smv[(2*sw) * 65 + dk], smv[(2*sw + 1) * 65 + dk], hi, lo);
        g_Vth[dbase + (size_t)dk * 1024 + sw] = hi;
        g_Vtl[dbase + (size_t)dk * 1024 + sw] = lo;
    }
}

// ---------------------------------------------------------------------------
// Flash attention (R12 config): bf16x3, Bc=128, cp.async double-buffered,
// P in registers, ldmatrix fragment loads. Emits O in tiled packed layout.
// ---------------------------------------------------------------------------
#define KWS 36
#define VWS 68
#define ATTN_SMEM_BYTES ((2*128*KWS*2 + 2*64*VWS*2) * 4)   // 143360

__global__ __launch_bounds__(256, 1)
void attn_fwd()
{
    extern __shared__ unsigned sm[];
    const unsigned smb  = (unsigned)__cvta_generic_to_shared(sm);
    const unsigned KshB = smb;
    const unsigned KslB = smb + 2*128*KWS*4;
    const unsigned VshB = KslB + 2*128*KWS*4;
    const unsigned VslB = VshB + 2*64*VWS*4;

    const int qb = (gridDim.x - 1) - blockIdx.x;
    const int bh = blockIdx.z * NHEADS + blockIdx.y;
    const int tid = threadIdx.x, warp = tid >> 5, lane = tid & 31;
    const int g = lane >> 2, t = lane & 3;
    const int kr0 = tid >> 3, kch = (tid & 7) * 4;
    const int vd0 = tid >> 4, vch = (tid & 15) * 4;

    const unsigned boffK = ldsm_b_off(lane, KWS);
    const unsigned boffV = ldsm_b_off(lane, VWS);

    auto load_kv = [&](int buf, int j) {
        const size_t kbase = ((size_t)bh * SEQ + (size_t)j * 128) * 32;
#pragma unroll
        for (int l = 0; l < 4; l++) {
            int r = kr0 + l * 32;
            unsigned doff = (unsigned)((r * KWS + kch) * 4);
            cpa16(KshB + buf*(128*KWS*4) + doff, g_Kh + kbase + r*32 + kch);
            cpa16(KslB + buf*(128*KWS*4) + doff, g_Kl + kbase + r*32 + kch);
        }
        const size_t vbase = (size_t)bh * DK * 1024 + (size_t)j * 64;
#pragma unroll
        for (int l = 0; l < 4; l++) {
            int dk = vd0 + l * 16;
            unsigned doff = (unsigned)((dk * VWS + vch) * 4);
            cpa16(VshB + buf*(64*VWS*4) + doff, g_Vth + vbase + (size_t)dk*1024 + vch);
            cpa16(VslB + buf*(64*VWS*4) + doff, g_Vtl + vbase + (size_t)dk*1024 + vch);
        }
        cpa_commit();
    };

    load_kv(0, 0);

    unsigned qh[4][4], ql[4][4];
    {
        const size_t qbase = ((size_t)bh * SEQ + (size_t)qb * 128 + warp * 16 + g) * 32;
#pragma unroll
        for (int kt = 0; kt < 4; kt++) {
            qh[kt][0] = g_Qh[qbase + kt*8 + t];
            qh[kt][1] = g_Qh[qbase + 8*32 + kt*8 + t];
            qh[kt][2] = g_Qh[qbase + kt*8 + 4 + t];
            qh[kt][3] = g_Qh[qbase + 8*32 + kt*8 + 4 + t];
            ql[kt][0] = g_Ql[qbase + kt*8 + t];
            ql[kt][1] = g_Ql[qbase + 8*32 + kt*8 + t];
            ql[kt][2] = g_Ql[qbase + kt*8 + 4 + t];
            ql[kt][3] = g_Ql[qbase + 8*32 + kt*8 + 4 + t];
        }
    }

    float m0 = -1e30f, m1 = -1e30f, l0 = 0.f, l1 = 0.f;
    float o[8][4];
#pragma unroll
    for (int ni = 0; ni < 8; ni++)
#pragma unroll
        for (int r = 0; r < 4; r++) o[ni][r] = 0.f;

    const int prow0 = warp * 16 + g;
    const int prow1 = prow0 + 8;

    cpa_wait0();
    __syncthreads();

    int buf = 0;
    for (int j = 0; j <= qb; j++) {
        if (j < qb) load_kv(buf ^ 1, j + 1);

        const unsigned KhB_t = KshB + (unsigned)(buf * 128*KWS*4);
        const unsigned KlB_t = KslB + (unsigned)(buf * 128*KWS*4);
        const unsigned VhB_t = VshB + (unsigned)(buf * 64*VWS*4);
        const unsigned VlB_t = VslB + (unsigned)(buf * 64*VWS*4);

        float s[16][4];
#pragma unroll
        for (int ni = 0; ni < 16; ni++) {
            s[ni][0] = 0.f; s[ni][1] = 0.f; s[ni][2] = 0.f; s[ni][3] = 0.f;
        }
#pragma unroll
        for (int kt = 0; kt < 4; kt++) {
#pragma unroll
            for (int p = 0; p < 8; p++) {
                unsigned nb = (unsigned)(p * 16 * KWS * 4) + (unsigned)(kt * 32);
                unsigned kh[4], kl[4];
                ldsm4(kh, KhB_t + nb + boffK);
                ldsm4(kl, KlB_t + nb + boffK);
                mma_bf16(s[2*p],   qh[kt], kh);
                mma_bf16(s[2*p],   qh[kt], kl);
                mma_bf16(s[2*p],   ql[kt], kh);
                mma_bf16(s[2*p+1], qh[kt], kh + 2);
                mma_bf16(s[2*p+1], qh[kt], kl + 2);
                mma_bf16(s[2*p+1], ql[kt], kh + 2);
            }
        }

        if (j == qb) {
#pragma unroll
            for (int ni = 0; ni < 16; ni++) {
                int cb = ni * 8 + 2 * t;
                if (cb     > prow0) s[ni][0] = -1e30f;
                if (cb + 1 > prow0) s[ni][1] = -1e30f;
                if (cb     > prow1) s[ni][2] = -1e30f;
                if (cb + 1 > prow1) s[ni][3] = -1e30f;
            }
        }

        float rm0 = -1e30f, rm1 = -1e30f;
#pragma unroll
        for (int ni = 0; ni < 16; ni++) {
            rm0 = fmaxf(rm0, fmaxf(s[ni][0], s[ni][1]));
            rm1 = fmaxf(rm1, fmaxf(s[ni][2], s[ni][3]));
        }
        rm0 = fmaxf(rm0, __shfl_xor_sync(0xffffffffu, rm0, 1));
        rm0 = fmaxf(rm0, __shfl_xor_sync(0xffffffffu, rm0, 2));
        rm1 = fmaxf(rm1, __shfl_xor_sync(0xffffffffu, rm1, 1));
        rm1 = fmaxf(rm1, __shfl_xor_sync(0xffffffffu, rm1, 2));

        float mn0 = fmaxf(m0, rm0), mn1 = fmaxf(m1, rm1);
        float a0 = ex2f(m0 - mn0), a1 = ex2f(m1 - mn1);
        float rs0 = 0.f, rs1 = 0.f;
#pragma unroll
        for (int ni = 0; ni < 16; ni++) {
            s[ni][0] = ex2f(s[ni][0] - mn0);
            s[ni][1] = ex2f(s[ni][1] - mn0);
            s[ni][2] = ex2f(s[ni][2] - mn1);
            s[ni][3] = ex2f(s[ni][3] - mn1);
            rs0 += s[ni][0] + s[ni][1];
            rs1 += s[ni][2] + s[ni][3];
        }
        rs0 += __shfl_xor_sync(0xffffffffu, rs0, 1);
        rs0 += __shfl_xor_sync(0xffffffffu, rs0, 2);
        rs1 += __shfl_xor_sync(0xffffffffu, rs1, 1);
        rs1 += __shfl_xor_sync(0xffffffffu, rs1, 2);
        l0 = l0 * a0 + rs0;  m0 = mn0;
        l1 = l1 * a1 + rs1;  m1 = mn1;
#pragma unroll
        for (int ni = 0; ni < 8; ni++) {
            o[ni][0] *= a0; o[ni][1] *= a0;
            o[ni][2] *= a1; o[ni][3] *= a1;
        }

#pragma unroll
        for (int kt = 0; kt < 8; kt++) {
            unsigned ph[4], pl[4];
            split2(s[2*kt][0],   s[2*kt][1],   ph[0], pl[0]);
            split2(s[2*kt][2],   s[2*kt][3],   ph[1], pl[1]);
            split2(s[2*kt+1][0], s[2*kt+1][1], ph[2], pl[2]);
            split2(s[2*kt+1][2], s[2*kt+1][3], ph[3], pl[3]);
#pragma unroll
            for (int p = 0; p < 4; p++) {
                unsigned nb = (unsigned)(p * 16 * VWS * 4) + (unsigned)(kt * 32);
                unsigned vh[4], vl[4];
                ldsm4(vh, VhB_t + nb + boffV);
                ldsm4(vl, VlB_t + nb + boffV);
                mma_bf16(o[2*p],   ph, vh);
                mma_bf16(o[2*p],   ph, vl);
                mma_bf16(o[2*p],   pl, vh);
                mma_bf16(o[2*p+1], ph, vh + 2);
                mma_bf16(o[2*p+1], ph, vl + 2);
                mma_bf16(o[2*p+1], pl, vh + 2);
            }
        }

        if (j < qb) cpa_wait0();
        __syncthreads();
        buf ^= 1;
    }

    // normalize + write O in tiled packed layout:
    // global row r = z*2048 + qb*128 + prow; rtile = r>>7 = z*16+qb;
    // col -> kt = col>>4, w8 = (col&15)>>1
    float inv0 = 1.f / l0, inv1 = 1.f / l1;
    const size_t rt = (size_t)(blockIdx.z * 16 + qb) * RTW;
    const int colb = blockIdx.y * DK;        // head offset within 1024
#pragma unroll
    for (int ni = 0; ni < 8; ni++) {
        int col = colb + ni * 8 + 2 * t;
        int kt = col >> 4, w8 = (col & 15) >> 1;
        unsigned hi, lo;
        split2(o[ni][0] * inv0, o[ni][1] * inv0, hi, lo);
        size_t w0 = rt + (((size_t)kt * 128 + prow0) * 8) + w8;
        g_Oth[w0] = hi; g_Otl[w0] = lo;
        split2(o[ni][2] * inv1, o[ni][3] * inv1, hi, lo);
        size_t w1 = rt + (((size_t)kt * 128 + prow1) * 8) + w8;
        g_Oth[w1] = hi; g_Otl[w1] = lo;
    }
}

// ---------------------------------------------------------------------------
extern "C" void kernel_launch(void* const* d_in, const int* in_sizes, int n_in,
                              void* d_out, int out_size)
{
    const float* x  = (const float*)d_in[0];
    const float* wq = (const float*)d_in[1];
    const float* wk = (const float*)d_in[2];
    const float* wv = (const float*)d_in[3];
    const float* wo = (const float*)d_in[4];
    float* out = (float*)d_out;

    unsigned *xth, *xtl, *wth, *wtl;
    cudaGetSymbolAddress((void**)&xth, g_Xth);
    cudaGetSymbolAddress((void**)&xtl, g_Xtl);
    cudaGetSymbolAddress((void**)&wth, g_Wth);
    cudaGetSymbolAddress((void**)&wtl, g_Wtl);

    cudaFuncSetAttribute(qkv_gemm,  cudaFuncAttributeMaxDynamicSharedMemorySize, GEMM_SMEM_BYTES);
    cudaFuncSetAttribute(proj_gemm, cudaFuncAttributeMaxDynamicSharedMemorySize, GEMM_SMEM_BYTES);
    cudaFuncSetAttribute(attn_fwd,  cudaFuncAttributeMaxDynamicSharedMemorySize, ATTN_SMEM_BYTES);

    const int XW = 32 * RTW;             // 2,097,152 words
    const int WW = 8 * RTW;              //   524,288 words
    pack_tiled<<<XW / 256, 256>>>(x,  xth, xtl, XW);
    pack_tiled<<<WW / 256, 256>>>(wq, wth + 0*(size_t)WW, wtl + 0*(size_t)WW, WW);
    pack_tiled<<<WW / 256, 256>>>(wk, wth + 1*(size_t)WW, wtl + 1*(size_t)WW, WW);
    pack_tiled<<<WW / 256, 256>>>(wv, wth + 2*(size_t)WW, wtl + 2*(size_t)WW, WW);
    pack_tiled<<<WW / 256, 256>>>(wo, wth + 3*(size_t)WW, wtl + 3*(size_t)WW, WW);

    dim3 gq(D_MODEL / 128, MROWS / 128, 3);          // (8,32,3)
    qkv_gemm<<<gq, 256, GEMM_SMEM_BYTES>>>();

    vtrans<<<dim3(SEQ / 128, NHEADS, BATCH), 256>>>();

    attn_fwd<<<dim3(SEQ / 128, NHEADS, BATCH), 256, ATTN_SMEM_BYTES>>>();

    dim3 gp(D_MODEL / 128, MROWS / 128);             // (8,32)
    proj_gemm<<<gp, 256, GEMM_SMEM_BYTES>>>(out);
}